// round 7
// baseline (speedup 1.0000x reference)
#include <cuda_runtime.h>
#include <cuda_fp16.h>
#include <math_constants.h>

#define N_NODES 50000
#define N_EDGES 1600000
#define IN_DIM  128
#define HEADS   4
#define HID     16
#define HD      64              // HEADS*HID
#define NEG_SLOPE 0.2f

// ---------------- scratch (device globals) ----------------------------------
__device__ __half g_feat_h[N_NODES * HD];   // projected features, fp16
__device__ float  g_el    [N_NODES * HEADS];
__device__ float  g_er    [N_NODES * HEADS];
__device__ int    g_src   [N_EDGES];
__device__ int    g_dst   [N_EDGES];
__device__ int    g_ssrc  [N_EDGES];        // src ids sorted by dst segment
__device__ int    g_cnt   [N_NODES];        // per-dst degree histogram
__device__ int    g_start [N_NODES + 1];    // exclusive prefix (segment starts)
__device__ int    g_cursor[N_NODES];        // mutable fill cursors

__device__ __forceinline__ float lrelu(float x) {
    return x > 0.0f ? x : NEG_SLOPE * x;
}

// ---------------- K0: zero histogram ----------------------------------------
__global__ void k_zero() {
    int i = blockIdx.x * blockDim.x + threadIdx.x;
    if (i < N_NODES) g_cnt[i] = 0;
}

// ---------------- K1: probe dtype, convert indices, build histogram ---------
__global__ void k_convert(const void* s_raw, const void* d_raw) {
    __shared__ int is64s;
    if (threadIdx.x == 0) is64s = 1;
    __syncthreads();
    {
        // If the data is really int32, these 64-bit words carry a random
        // index in the upper half — guaranteed >= N_NODES among 256 samples.
        unsigned long long v = ((const unsigned long long*)s_raw)[threadIdx.x];
        if (v >= (unsigned long long)N_NODES) atomicExch(&is64s, 0);
    }
    __syncthreads();
    const bool is64 = (is64s != 0);

    int i = blockIdx.x * blockDim.x + threadIdx.x;
    if (i >= N_EDGES) return;
    int s, d;
    if (is64) {
        s = (int)((const long long*)s_raw)[i];
        d = (int)((const long long*)d_raw)[i];
    } else {
        s = ((const int*)s_raw)[i];
        d = ((const int*)d_raw)[i];
    }
    g_src[i] = s;
    g_dst[i] = d;
    atomicAdd(&g_cnt[d], 1);
}

// ---------------- K2: single-block exclusive scan over g_cnt ----------------
#define SCAN_T 1024
#define CHUNK  49              // 1024*49 = 50176 >= N_NODES
__global__ void __launch_bounds__(SCAN_T) k_prefix() {
    __shared__ int sums[SCAN_T];
    int t = threadIdx.x;
    int base = t * CHUNK;
    int local = 0;
    #pragma unroll 7
    for (int k = 0; k < CHUNK; k++) {
        int idx = base + k;
        if (idx < N_NODES) local += g_cnt[idx];
    }
    sums[t] = local;
    __syncthreads();
    // Hillis-Steele inclusive scan
    for (int off = 1; off < SCAN_T; off <<= 1) {
        int v = (t >= off) ? sums[t - off] : 0;
        __syncthreads();
        sums[t] += v;
        __syncthreads();
    }
    int run = (t == 0) ? 0 : sums[t - 1];
    #pragma unroll 7
    for (int k = 0; k < CHUNK; k++) {
        int idx = base + k;
        if (idx < N_NODES) {
            g_start[idx]  = run;
            g_cursor[idx] = run;
            run += g_cnt[idx];
        }
    }
    if (t == SCAN_T - 1) g_start[N_NODES] = run;
}

// ---------------- K3: fill sorted edge list ----------------------------------
__global__ void k_fill() {
    int i = blockIdx.x * blockDim.x + threadIdx.x;
    if (i >= N_EDGES) return;
    int d = g_dst[i];
    int pos = atomicAdd(&g_cursor[d], 1);
    g_ssrc[pos] = g_src[i];
}

// ---------------- K4: GEMM feat = X @ W, fused el/er + fp16 store -----------
#define BM 64
#define KC 64
#define XPAD 68

__global__ void __launch_bounds__(256) k_gemm(const float* __restrict__ X,
                                              const float* __restrict__ W,
                                              const float* __restrict__ attn_l,
                                              const float* __restrict__ attn_r) {
    __shared__ float sW [KC * HD];     // 16 KB
    __shared__ float sXt[KC * XPAD];   // 17 KB
    const int tid  = threadIdx.x;
    const int row0 = blockIdx.x * BM;
    const int r0   = (tid >> 4) << 2;
    const int c0   = (tid & 15) << 2;

    float acc[4][4] = {};

    for (int k0 = 0; k0 < IN_DIM; k0 += KC) {
        #pragma unroll
        for (int i = tid; i < KC * HD; i += 256) {
            int k = i >> 6, c = i & 63;
            sW[i] = W[(k0 + k) * HD + c];
        }
        #pragma unroll
        for (int i = tid; i < BM * KC; i += 256) {
            int r = i >> 6, k = i & 63;
            int gr = row0 + r;
            float v = (gr < N_NODES) ? X[gr * IN_DIM + k0 + k] : 0.0f;
            sXt[k * XPAD + r] = v;
        }
        __syncthreads();

        #pragma unroll 8
        for (int k = 0; k < KC; k++) {
            float4 xv = *(const float4*)&sXt[k * XPAD + r0];
            float4 wv = *(const float4*)&sW [k * HD   + c0];
            acc[0][0] = fmaf(xv.x, wv.x, acc[0][0]);
            acc[0][1] = fmaf(xv.x, wv.y, acc[0][1]);
            acc[0][2] = fmaf(xv.x, wv.z, acc[0][2]);
            acc[0][3] = fmaf(xv.x, wv.w, acc[0][3]);
            acc[1][0] = fmaf(xv.y, wv.x, acc[1][0]);
            acc[1][1] = fmaf(xv.y, wv.y, acc[1][1]);
            acc[1][2] = fmaf(xv.y, wv.z, acc[1][2]);
            acc[1][3] = fmaf(xv.y, wv.w, acc[1][3]);
            acc[2][0] = fmaf(xv.z, wv.x, acc[2][0]);
            acc[2][1] = fmaf(xv.z, wv.y, acc[2][1]);
            acc[2][2] = fmaf(xv.z, wv.z, acc[2][2]);
            acc[2][3] = fmaf(xv.z, wv.w, acc[2][3]);
            acc[3][0] = fmaf(xv.w, wv.x, acc[3][0]);
            acc[3][1] = fmaf(xv.w, wv.y, acc[3][1]);
            acc[3][2] = fmaf(xv.w, wv.z, acc[3][2]);
            acc[3][3] = fmaf(xv.w, wv.w, acc[3][3]);
        }
        __syncthreads();
    }

    const float4 al4 = *(const float4*)&attn_l[c0];
    const float4 ar4 = *(const float4*)&attn_r[c0];
    const int head = (tid >> 2) & 3;

    #pragma unroll
    for (int i = 0; i < 4; i++) {
        int r = row0 + r0 + i;
        if (r < N_NODES) {
            __half2 h0 = __float22half2_rn(make_float2(acc[i][0], acc[i][1]));
            __half2 h1 = __float22half2_rn(make_float2(acc[i][2], acc[i][3]));
            uint2 pk = make_uint2(*(unsigned*)&h0, *(unsigned*)&h1);
            *(uint2*)&g_feat_h[r * HD + c0] = pk;
        }

        float el = acc[i][0] * al4.x + acc[i][1] * al4.y
                 + acc[i][2] * al4.z + acc[i][3] * al4.w;
        float er = acc[i][0] * ar4.x + acc[i][1] * ar4.y
                 + acc[i][2] * ar4.z + acc[i][3] * ar4.w;
        el += __shfl_xor_sync(0xffffffffu, el, 1);
        el += __shfl_xor_sync(0xffffffffu, el, 2);
        er += __shfl_xor_sync(0xffffffffu, er, 1);
        er += __shfl_xor_sync(0xffffffffu, er, 2);
        if ((tid & 3) == 0 && r < N_NODES) {
            g_el[r * HEADS + head] = el;
            g_er[r * HEADS + head] = er;
        }
    }
}

// ---------------- K5: warp-per-node aggregation (zero atomics) ---------------
// Warp owns dst node n. 4 edges in flight per iteration: 8-lane group g
// handles edge (beg+g, beg+g+4, ...). Lane p (0..7) within a group owns
// halfs [8p, 8p+8) of the feature row (one uint4), head = p>>1. Full row
// accumulates in registers; normalize + head-mean via shuffles at the end.
__global__ void __launch_bounds__(256) k_agg(const float* __restrict__ bias,
                                             float* __restrict__ out) {
    int warp = (blockIdx.x * blockDim.x + threadIdx.x) >> 5;
    if (warp >= N_NODES) return;
    const int n    = warp;
    const int lane = threadIdx.x & 31;
    const int g    = lane >> 3;
    const int p    = lane & 7;
    const int h    = p >> 1;

    const int beg = g_start[n];
    const int end = g_start[n + 1];

    const float er_h = g_er[n * HEADS + h];

    float acc[8] = {};
    float den = 0.0f;

    for (int i = beg + g; i < end; i += 4) {
        int s = g_ssrc[i];
        float ee = __expf(lrelu(g_el[s * HEADS + h] + er_h));
        uint4 pk = *(const uint4*)&g_feat_h[s * HD + p * 8];
        float2 f0 = __half22float2(*(__half2*)&pk.x);
        float2 f1 = __half22float2(*(__half2*)&pk.y);
        float2 f2 = __half22float2(*(__half2*)&pk.z);
        float2 f3 = __half22float2(*(__half2*)&pk.w);
        acc[0] = fmaf(f0.x, ee, acc[0]);
        acc[1] = fmaf(f0.y, ee, acc[1]);
        acc[2] = fmaf(f1.x, ee, acc[2]);
        acc[3] = fmaf(f1.y, ee, acc[3]);
        acc[4] = fmaf(f2.x, ee, acc[4]);
        acc[5] = fmaf(f2.y, ee, acc[5]);
        acc[6] = fmaf(f3.x, ee, acc[6]);
        acc[7] = fmaf(f3.y, ee, acc[7]);
        den += ee;
    }

    // reduce the 4 edge-groups (lanes with same p): xor 8, xor 16
    #pragma unroll
    for (int k = 0; k < 8; k++) {
        acc[k] += __shfl_xor_sync(0xffffffffu, acc[k], 8);
        acc[k] += __shfl_xor_sync(0xffffffffu, acc[k], 16);
    }
    den += __shfl_xor_sync(0xffffffffu, den, 8);
    den += __shfl_xor_sync(0xffffffffu, den, 16);

    // normalize per head (den duplicated across lanes of same head)
    float inv = (den > 0.0f) ? __fdividef(0.25f, den) : 0.0f;
    #pragma unroll
    for (int k = 0; k < 8; k++) acc[k] *= inv;

    // head-mean: lane p's floats have output dd = (p&1)*8 + k; heads differ
    // by p xor 2 and p xor 4 — sum them after normalization.
    #pragma unroll
    for (int k = 0; k < 8; k++) {
        acc[k] += __shfl_xor_sync(0xffffffffu, acc[k], 2);
        acc[k] += __shfl_xor_sync(0xffffffffu, acc[k], 4);
    }

    // lanes 0,1 hold the 16 outputs (dd = lane*8 + k); add bias head-mean
    if (lane < 2) {
        float4 o0, o1;
        float* oo = (float*)&o0;
        #pragma unroll
        for (int k = 0; k < 8; k++) {
            int dd = lane * 8 + k;
            float bm = 0.25f * (bias[dd] + bias[HID + dd]
                              + bias[2 * HID + dd] + bias[3 * HID + dd]);
            if (k < 4) ((float*)&o0)[k] = acc[k] + bm;
            else       ((float*)&o1)[k - 4] = acc[k] + bm;
        }
        (void)oo;
        *(float4*)&out[n * HID + lane * 8]     = o0;
        *(float4*)&out[n * HID + lane * 8 + 4] = o1;
    }
}

// ---------------- launch ------------------------------------------------------
extern "C" void kernel_launch(void* const* d_in, const int* in_sizes, int n_in,
                              void* d_out, int out_size) {
    const float* features = (const float*)d_in[0];
    const float* W        = (const float*)d_in[1];
    const float* attn_l   = (const float*)d_in[2];
    const float* attn_r   = (const float*)d_in[3];
    const float* bias     = (const float*)d_in[4];
    const void*  src_raw  = d_in[5];
    const void*  dst_raw  = d_in[6];
    float* out = (float*)d_out;

    const int T = 256;

    k_zero   <<<(N_NODES + T - 1) / T, T>>>();
    k_convert<<<(N_EDGES + T - 1) / T, T>>>(src_raw, dst_raw);
    k_gemm   <<<(N_NODES + BM - 1) / BM, T>>>(features, W, attn_l, attn_r);
    k_prefix <<<1, SCAN_T>>>();
    k_fill   <<<(N_EDGES + T - 1) / T, T>>>();
    k_agg    <<<(N_NODES * 32 + T - 1) / T, T>>>(bias, out);
}

// round 8
// speedup vs baseline: 1.6375x; 1.6375x over previous
#include <cuda_runtime.h>
#include <cuda_fp16.h>
#include <math_constants.h>

#define N_NODES 50000
#define N_EDGES 1600000
#define IN_DIM  128
#define HEADS   4
#define HID     16
#define HD      64              // HEADS*HID
#define NEG_SLOPE 0.2f

#define SCAN_ELEMS 1024                       // counts per scan block
#define SCAN_BLOCKS ((N_NODES + SCAN_ELEMS - 1) / SCAN_ELEMS)   // 49

// ---------------- scratch (device globals) ----------------------------------
__device__ __half g_feat_h[N_NODES * HD];   // projected features, fp16
__device__ float  g_el    [N_NODES * HEADS];
__device__ float  g_er    [N_NODES * HEADS];
__device__ int    g_src   [N_EDGES];
__device__ int    g_dst   [N_EDGES];
__device__ int    g_ssrc  [N_EDGES];        // src ids sorted by dst segment
__device__ int    g_cnt   [SCAN_BLOCKS * SCAN_ELEMS];  // histogram (padded)
__device__ int    g_part  [SCAN_BLOCKS];    // per-block sums
__device__ int    g_start [N_NODES + 1];    // exclusive prefix (segment starts)
__device__ int    g_cursor[N_NODES];        // mutable fill cursors

__device__ __forceinline__ float lrelu(float x) {
    return x > 0.0f ? x : NEG_SLOPE * x;
}

// ---------------- K0: zero histogram (padded region too) --------------------
__global__ void k_zero() {
    int i = blockIdx.x * blockDim.x + threadIdx.x;
    if (i < SCAN_BLOCKS * SCAN_ELEMS) g_cnt[i] = 0;
}

// ---------------- K1: probe dtype, convert indices, build histogram ---------
__global__ void k_convert(const void* s_raw, const void* d_raw) {
    __shared__ int is64s;
    if (threadIdx.x == 0) is64s = 1;
    __syncthreads();
    {
        // If the data is really int32, these 64-bit words carry a random
        // index in the upper half — guaranteed >= N_NODES among 256 samples.
        unsigned long long v = ((const unsigned long long*)s_raw)[threadIdx.x];
        if (v >= (unsigned long long)N_NODES) atomicExch(&is64s, 0);
    }
    __syncthreads();
    const bool is64 = (is64s != 0);

    int i = blockIdx.x * blockDim.x + threadIdx.x;
    if (i >= N_EDGES) return;
    int s, d;
    if (is64) {
        s = (int)((const long long*)s_raw)[i];
        d = (int)((const long long*)d_raw)[i];
    } else {
        s = ((const int*)s_raw)[i];
        d = ((const int*)d_raw)[i];
    }
    g_src[i] = s;
    g_dst[i] = d;
    atomicAdd(&g_cnt[d], 1);
}

// ---------------- scan phase 1: per-block sums (49 blocks x 1024 counts) ----
__global__ void __launch_bounds__(256) k_scan1() {
    int b = blockIdx.x, t = threadIdx.x;
    int4 v = ((const int4*)g_cnt)[b * 256 + t];
    int s = v.x + v.y + v.z + v.w;
    // warp reduce
    #pragma unroll
    for (int o = 16; o > 0; o >>= 1) s += __shfl_xor_sync(0xffffffffu, s, o);
    __shared__ int ws[8];
    if ((t & 31) == 0) ws[t >> 5] = s;
    __syncthreads();
    if (t < 8) {
        int x = ws[t];
        #pragma unroll
        for (int o = 4; o > 0; o >>= 1) x += __shfl_xor_sync(0xffu, x, o);
        if (t == 0) g_part[b] = x;
    }
}

// ---------------- scan phase 2: exclusive scan of 49 partials (one warp) ----
__global__ void k_scan2() {
    int t = threadIdx.x;                       // 64 threads
    int v = (t < SCAN_BLOCKS) ? g_part[t] : 0;
    // inclusive scan across 64 lanes via two warps + shared
    __shared__ int sh[64];
    sh[t] = v;
    __syncthreads();
    for (int o = 1; o < 64; o <<= 1) {
        int add = (t >= o) ? sh[t - o] : 0;
        __syncthreads();
        sh[t] += add;
        __syncthreads();
    }
    if (t < SCAN_BLOCKS) g_part[t] = (t == 0) ? 0 : sh[t - 1];   // exclusive
    if (t == 63) g_start[N_NODES] = sh[SCAN_BLOCKS - 1];          // total
}

// ---------------- scan phase 3: block rescan + offset, write start/cursor ---
__global__ void __launch_bounds__(256) k_scan3() {
    int b = blockIdx.x, t = threadIdx.x;
    int base = b * SCAN_ELEMS + t * 4;
    int4 v = ((const int4*)g_cnt)[b * 256 + t];
    int tsum = v.x + v.y + v.z + v.w;

    // warp-level inclusive scan of thread sums
    int lane = t & 31, w = t >> 5;
    int inc = tsum;
    #pragma unroll
    for (int o = 1; o < 32; o <<= 1) {
        int x = __shfl_up_sync(0xffffffffu, inc, o);
        if (lane >= o) inc += x;
    }
    __shared__ int wsum[8];
    if (lane == 31) wsum[w] = inc;
    __syncthreads();
    if (t < 8) {
        int x = wsum[t];
        #pragma unroll
        for (int o = 1; o < 8; o <<= 1) {
            int y = __shfl_up_sync(0xffu, x, o);
            if (t >= o) x += y;
        }
        wsum[t] = x;
    }
    __syncthreads();
    int off = g_part[b] + (inc - tsum) + ((w > 0) ? wsum[w - 1] : 0);

    int run = off;
    #pragma unroll
    for (int k = 0; k < 4; k++) {
        int idx = base + k;
        if (idx < N_NODES) {
            g_start[idx]  = run;
            g_cursor[idx] = run;
        }
        run += ((const int*)&v)[k];
    }
}

// ---------------- K3: fill sorted edge list ----------------------------------
__global__ void k_fill() {
    int i = blockIdx.x * blockDim.x + threadIdx.x;
    if (i >= N_EDGES) return;
    int d = g_dst[i];
    int pos = atomicAdd(&g_cursor[d], 1);
    g_ssrc[pos] = g_src[i];
}

// ---------------- K4: GEMM feat = X @ W, fused el/er + fp16 store -----------
#define BM 64
#define KC 64
#define XPAD 68

__global__ void __launch_bounds__(256) k_gemm(const float* __restrict__ X,
                                              const float* __restrict__ W,
                                              const float* __restrict__ attn_l,
                                              const float* __restrict__ attn_r) {
    __shared__ float sW [KC * HD];     // 16 KB
    __shared__ float sXt[KC * XPAD];   // 17 KB
    const int tid  = threadIdx.x;
    const int row0 = blockIdx.x * BM;
    const int r0   = (tid >> 4) << 2;
    const int c0   = (tid & 15) << 2;

    float acc[4][4] = {};

    for (int k0 = 0; k0 < IN_DIM; k0 += KC) {
        #pragma unroll
        for (int i = tid; i < KC * HD; i += 256) {
            int k = i >> 6, c = i & 63;
            sW[i] = W[(k0 + k) * HD + c];
        }
        #pragma unroll
        for (int i = tid; i < BM * KC; i += 256) {
            int r = i >> 6, k = i & 63;
            int gr = row0 + r;
            float v = (gr < N_NODES) ? X[gr * IN_DIM + k0 + k] : 0.0f;
            sXt[k * XPAD + r] = v;
        }
        __syncthreads();

        #pragma unroll 8
        for (int k = 0; k < KC; k++) {
            float4 xv = *(const float4*)&sXt[k * XPAD + r0];
            float4 wv = *(const float4*)&sW [k * HD   + c0];
            acc[0][0] = fmaf(xv.x, wv.x, acc[0][0]);
            acc[0][1] = fmaf(xv.x, wv.y, acc[0][1]);
            acc[0][2] = fmaf(xv.x, wv.z, acc[0][2]);
            acc[0][3] = fmaf(xv.x, wv.w, acc[0][3]);
            acc[1][0] = fmaf(xv.y, wv.x, acc[1][0]);
            acc[1][1] = fmaf(xv.y, wv.y, acc[1][1]);
            acc[1][2] = fmaf(xv.y, wv.z, acc[1][2]);
            acc[1][3] = fmaf(xv.y, wv.w, acc[1][3]);
            acc[2][0] = fmaf(xv.z, wv.x, acc[2][0]);
            acc[2][1] = fmaf(xv.z, wv.y, acc[2][1]);
            acc[2][2] = fmaf(xv.z, wv.z, acc[2][2]);
            acc[2][3] = fmaf(xv.z, wv.w, acc[2][3]);
            acc[3][0] = fmaf(xv.w, wv.x, acc[3][0]);
            acc[3][1] = fmaf(xv.w, wv.y, acc[3][1]);
            acc[3][2] = fmaf(xv.w, wv.z, acc[3][2]);
            acc[3][3] = fmaf(xv.w, wv.w, acc[3][3]);
        }
        __syncthreads();
    }

    const float4 al4 = *(const float4*)&attn_l[c0];
    const float4 ar4 = *(const float4*)&attn_r[c0];
    const int head = (tid >> 2) & 3;

    #pragma unroll
    for (int i = 0; i < 4; i++) {
        int r = row0 + r0 + i;
        if (r < N_NODES) {
            __half2 h0 = __float22half2_rn(make_float2(acc[i][0], acc[i][1]));
            __half2 h1 = __float22half2_rn(make_float2(acc[i][2], acc[i][3]));
            uint2 pk = make_uint2(*(unsigned*)&h0, *(unsigned*)&h1);
            *(uint2*)&g_feat_h[r * HD + c0] = pk;
        }

        float el = acc[i][0] * al4.x + acc[i][1] * al4.y
                 + acc[i][2] * al4.z + acc[i][3] * al4.w;
        float er = acc[i][0] * ar4.x + acc[i][1] * ar4.y
                 + acc[i][2] * ar4.z + acc[i][3] * ar4.w;
        el += __shfl_xor_sync(0xffffffffu, el, 1);
        el += __shfl_xor_sync(0xffffffffu, el, 2);
        er += __shfl_xor_sync(0xffffffffu, er, 1);
        er += __shfl_xor_sync(0xffffffffu, er, 2);
        if ((tid & 3) == 0 && r < N_NODES) {
            g_el[r * HEADS + head] = el;
            g_er[r * HEADS + head] = er;
        }
    }
}

// ---------------- K5: warp-per-node aggregation (zero atomics) ---------------
__global__ void __launch_bounds__(256) k_agg(const float* __restrict__ bias,
                                             float* __restrict__ out) {
    int warp = (blockIdx.x * blockDim.x + threadIdx.x) >> 5;
    if (warp >= N_NODES) return;
    const int n    = warp;
    const int lane = threadIdx.x & 31;
    const int g    = lane >> 3;
    const int p    = lane & 7;
    const int h    = p >> 1;

    const int beg = g_start[n];
    const int end = g_start[n + 1];

    const float er_h = g_er[n * HEADS + h];

    float acc[8] = {};
    float den = 0.0f;

    for (int i = beg + g; i < end; i += 4) {
        int s = g_ssrc[i];
        float ee = __expf(lrelu(g_el[s * HEADS + h] + er_h));
        uint4 pk = *(const uint4*)&g_feat_h[s * HD + p * 8];
        float2 f0 = __half22float2(*(__half2*)&pk.x);
        float2 f1 = __half22float2(*(__half2*)&pk.y);
        float2 f2 = __half22float2(*(__half2*)&pk.z);
        float2 f3 = __half22float2(*(__half2*)&pk.w);
        acc[0] = fmaf(f0.x, ee, acc[0]);
        acc[1] = fmaf(f0.y, ee, acc[1]);
        acc[2] = fmaf(f1.x, ee, acc[2]);
        acc[3] = fmaf(f1.y, ee, acc[3]);
        acc[4] = fmaf(f2.x, ee, acc[4]);
        acc[5] = fmaf(f2.y, ee, acc[5]);
        acc[6] = fmaf(f3.x, ee, acc[6]);
        acc[7] = fmaf(f3.y, ee, acc[7]);
        den += ee;
    }

    // reduce the 4 edge-groups (lanes with same p): xor 8, xor 16
    #pragma unroll
    for (int k = 0; k < 8; k++) {
        acc[k] += __shfl_xor_sync(0xffffffffu, acc[k], 8);
        acc[k] += __shfl_xor_sync(0xffffffffu, acc[k], 16);
    }
    den += __shfl_xor_sync(0xffffffffu, den, 8);
    den += __shfl_xor_sync(0xffffffffu, den, 16);

    // normalize per head
    float inv = (den > 0.0f) ? __fdividef(0.25f, den) : 0.0f;
    #pragma unroll
    for (int k = 0; k < 8; k++) acc[k] *= inv;

    // head-mean: heads differ by p xor 2 and p xor 4
    #pragma unroll
    for (int k = 0; k < 8; k++) {
        acc[k] += __shfl_xor_sync(0xffffffffu, acc[k], 2);
        acc[k] += __shfl_xor_sync(0xffffffffu, acc[k], 4);
    }

    // lanes 0,1 hold the 16 outputs (dd = lane*8 + k); add bias head-mean
    if (lane < 2) {
        float4 o0, o1;
        #pragma unroll
        for (int k = 0; k < 8; k++) {
            int dd = lane * 8 + k;
            float bm = 0.25f * (bias[dd] + bias[HID + dd]
                              + bias[2 * HID + dd] + bias[3 * HID + dd]);
            if (k < 4) ((float*)&o0)[k] = acc[k] + bm;
            else       ((float*)&o1)[k - 4] = acc[k] + bm;
        }
        *(float4*)&out[n * HID + lane * 8]     = o0;
        *(float4*)&out[n * HID + lane * 8 + 4] = o1;
    }
}

// ---------------- launch ------------------------------------------------------
extern "C" void kernel_launch(void* const* d_in, const int* in_sizes, int n_in,
                              void* d_out, int out_size) {
    const float* features = (const float*)d_in[0];
    const float* W        = (const float*)d_in[1];
    const float* attn_l   = (const float*)d_in[2];
    const float* attn_r   = (const float*)d_in[3];
    const float* bias     = (const float*)d_in[4];
    const void*  src_raw  = d_in[5];
    const void*  dst_raw  = d_in[6];
    float* out = (float*)d_out;

    const int T = 256;

    k_zero   <<<(SCAN_BLOCKS * SCAN_ELEMS + T - 1) / T, T>>>();
    k_convert<<<(N_EDGES + T - 1) / T, T>>>(src_raw, dst_raw);
    k_scan1  <<<SCAN_BLOCKS, T>>>();
    k_scan2  <<<1, 64>>>();
    k_scan3  <<<SCAN_BLOCKS, T>>>();
    k_fill   <<<(N_EDGES + T - 1) / T, T>>>();
    k_gemm   <<<(N_NODES + BM - 1) / BM, T>>>(features, W, attn_l, attn_r);
    k_agg    <<<(N_NODES * 32 + T - 1) / T, T>>>(bias, out);
}

// round 9
// speedup vs baseline: 1.7589x; 1.0741x over previous
#include <cuda_runtime.h>
#include <cuda_fp16.h>
#include <math_constants.h>

#define N_NODES 50000
#define N_EDGES 1600000
#define IN_DIM  128
#define HEADS   4
#define HID     16
#define HD      64              // HEADS*HID
#define NEG_SLOPE 0.2f

#define SCAN_ELEMS 1024                       // counts per scan block
#define SCAN_BLOCKS ((N_NODES + SCAN_ELEMS - 1) / SCAN_ELEMS)   // 49

// ---------------- scratch (device globals) ----------------------------------
__device__ __half g_feat_h[N_NODES * HD];   // projected features, fp16
__device__ float  g_el    [N_NODES * HEADS];
__device__ float  g_er    [N_NODES * HEADS];
__device__ int    g_src   [N_EDGES];
__device__ int    g_dst   [N_EDGES];
__device__ int    g_ssrc  [N_EDGES];        // src ids sorted by dst segment
__device__ int    g_cnt   [SCAN_BLOCKS * SCAN_ELEMS];  // histogram (padded)
__device__ int    g_part  [SCAN_BLOCKS];    // per-block sums
__device__ int    g_start [N_NODES + 1];    // exclusive prefix (segment starts)
__device__ int    g_cursor[N_NODES];        // mutable fill cursors

__device__ __forceinline__ float lrelu(float x) {
    return x > 0.0f ? x : NEG_SLOPE * x;
}

// ---------------- K0: zero histogram (padded region too) --------------------
__global__ void k_zero() {
    int i = blockIdx.x * blockDim.x + threadIdx.x;
    if (i < SCAN_BLOCKS * SCAN_ELEMS) g_cnt[i] = 0;
}

// ---------------- K1: probe dtype, convert indices, build histogram ---------
__global__ void k_convert(const void* s_raw, const void* d_raw) {
    __shared__ int is64s;
    if (threadIdx.x == 0) is64s = 1;
    __syncthreads();
    {
        // If the data is really int32, these 64-bit words carry a random
        // index in the upper half — guaranteed >= N_NODES among 256 samples.
        unsigned long long v = ((const unsigned long long*)s_raw)[threadIdx.x];
        if (v >= (unsigned long long)N_NODES) atomicExch(&is64s, 0);
    }
    __syncthreads();
    const bool is64 = (is64s != 0);

    int i = blockIdx.x * blockDim.x + threadIdx.x;
    if (i >= N_EDGES) return;
    int s, d;
    if (is64) {
        s = (int)((const long long*)s_raw)[i];
        d = (int)((const long long*)d_raw)[i];
    } else {
        s = ((const int*)s_raw)[i];
        d = ((const int*)d_raw)[i];
    }
    g_src[i] = s;
    g_dst[i] = d;
    atomicAdd(&g_cnt[d], 1);
}

// ---------------- scan phase 1: per-block sums (49 blocks x 1024 counts) ----
__global__ void __launch_bounds__(256) k_scan1() {
    int b = blockIdx.x, t = threadIdx.x;
    int4 v = ((const int4*)g_cnt)[b * 256 + t];
    int s = v.x + v.y + v.z + v.w;
    #pragma unroll
    for (int o = 16; o > 0; o >>= 1) s += __shfl_xor_sync(0xffffffffu, s, o);
    __shared__ int ws[8];
    if ((t & 31) == 0) ws[t >> 5] = s;
    __syncthreads();
    if (t < 8) {
        int x = ws[t];
        #pragma unroll
        for (int o = 4; o > 0; o >>= 1) x += __shfl_xor_sync(0xffu, x, o);
        if (t == 0) g_part[b] = x;
    }
}

// ---------------- scan phase 2+3 fused: every block redundantly scans the
// 49 partials with one warp, then rescans its own 1024 counts with offset ----
__global__ void __launch_bounds__(256) k_scan3() {
    __shared__ int sh[SCAN_BLOCKS];   // inclusive scan of partials
    __shared__ int wsum[8];
    int b = blockIdx.x, t = threadIdx.x;
    int lane = t & 31, w = t >> 5;

    if (t < 32) {
        int a0 = (t < SCAN_BLOCKS) ? g_part[t] : 0;
        int a1 = (t + 32 < SCAN_BLOCKS) ? g_part[t + 32] : 0;
        int i0 = a0;
        #pragma unroll
        for (int o = 1; o < 32; o <<= 1) {
            int x = __shfl_up_sync(0xffffffffu, i0, o);
            if (lane >= o) i0 += x;
        }
        int totLow = __shfl_sync(0xffffffffu, i0, 31);
        int i1 = a1;
        #pragma unroll
        for (int o = 1; o < 32; o <<= 1) {
            int x = __shfl_up_sync(0xffffffffu, i1, o);
            if (lane >= o) i1 += x;
        }
        i1 += totLow;
        if (t < SCAN_BLOCKS) sh[t] = i0;
        if (t + 32 < SCAN_BLOCKS) sh[t + 32] = i1;
    }
    __syncthreads();

    const int blockOff = (b == 0) ? 0 : sh[b - 1];
    if (b == SCAN_BLOCKS - 1 && t == 0) g_start[N_NODES] = sh[SCAN_BLOCKS - 1];

    int base = b * SCAN_ELEMS + t * 4;
    int4 v = ((const int4*)g_cnt)[b * 256 + t];
    int tsum = v.x + v.y + v.z + v.w;

    int inc = tsum;
    #pragma unroll
    for (int o = 1; o < 32; o <<= 1) {
        int x = __shfl_up_sync(0xffffffffu, inc, o);
        if (lane >= o) inc += x;
    }
    if (lane == 31) wsum[w] = inc;
    __syncthreads();
    if (t < 8) {
        int x = wsum[t];
        #pragma unroll
        for (int o = 1; o < 8; o <<= 1) {
            int y = __shfl_up_sync(0xffu, x, o);
            if (t >= o) x += y;
        }
        wsum[t] = x;
    }
    __syncthreads();
    int off = blockOff + (inc - tsum) + ((w > 0) ? wsum[w - 1] : 0);

    int run = off;
    #pragma unroll
    for (int k = 0; k < 4; k++) {
        int idx = base + k;
        if (idx < N_NODES) {
            g_start[idx]  = run;
            g_cursor[idx] = run;
        }
        run += ((const int*)&v)[k];
    }
}

// ---------------- K3: fill sorted edge list ----------------------------------
__global__ void k_fill() {
    int i = blockIdx.x * blockDim.x + threadIdx.x;
    if (i >= N_EDGES) return;
    int d = g_dst[i];
    int pos = atomicAdd(&g_cursor[d], 1);
    g_ssrc[pos] = g_src[i];
}

// ---------------- K4: GEMM feat = X @ W, fused el/er + fp16 store -----------
#define BM 64
#define KC 64
#define XPAD 68

__global__ void __launch_bounds__(256) k_gemm(const float* __restrict__ X,
                                              const float* __restrict__ W,
                                              const float* __restrict__ attn_l,
                                              const float* __restrict__ attn_r) {
    __shared__ float sW [KC * HD];
    __shared__ float sXt[KC * XPAD];
    const int tid  = threadIdx.x;
    const int row0 = blockIdx.x * BM;
    const int r0   = (tid >> 4) << 2;
    const int c0   = (tid & 15) << 2;

    float acc[4][4] = {};

    for (int k0 = 0; k0 < IN_DIM; k0 += KC) {
        #pragma unroll
        for (int i = tid; i < KC * HD; i += 256) {
            int k = i >> 6, c = i & 63;
            sW[i] = W[(k0 + k) * HD + c];
        }
        #pragma unroll
        for (int i = tid; i < BM * KC; i += 256) {
            int r = i >> 6, k = i & 63;
            int gr = row0 + r;
            float v = (gr < N_NODES) ? X[gr * IN_DIM + k0 + k] : 0.0f;
            sXt[k * XPAD + r] = v;
        }
        __syncthreads();

        #pragma unroll 8
        for (int k = 0; k < KC; k++) {
            float4 xv = *(const float4*)&sXt[k * XPAD + r0];
            float4 wv = *(const float4*)&sW [k * HD   + c0];
            acc[0][0] = fmaf(xv.x, wv.x, acc[0][0]);
            acc[0][1] = fmaf(xv.x, wv.y, acc[0][1]);
            acc[0][2] = fmaf(xv.x, wv.z, acc[0][2]);
            acc[0][3] = fmaf(xv.x, wv.w, acc[0][3]);
            acc[1][0] = fmaf(xv.y, wv.x, acc[1][0]);
            acc[1][1] = fmaf(xv.y, wv.y, acc[1][1]);
            acc[1][2] = fmaf(xv.y, wv.z, acc[1][2]);
            acc[1][3] = fmaf(xv.y, wv.w, acc[1][3]);
            acc[2][0] = fmaf(xv.z, wv.x, acc[2][0]);
            acc[2][1] = fmaf(xv.z, wv.y, acc[2][1]);
            acc[2][2] = fmaf(xv.z, wv.z, acc[2][2]);
            acc[2][3] = fmaf(xv.z, wv.w, acc[2][3]);
            acc[3][0] = fmaf(xv.w, wv.x, acc[3][0]);
            acc[3][1] = fmaf(xv.w, wv.y, acc[3][1]);
            acc[3][2] = fmaf(xv.w, wv.z, acc[3][2]);
            acc[3][3] = fmaf(xv.w, wv.w, acc[3][3]);
        }
        __syncthreads();
    }

    const float4 al4 = *(const float4*)&attn_l[c0];
    const float4 ar4 = *(const float4*)&attn_r[c0];
    const int head = (tid >> 2) & 3;

    #pragma unroll
    for (int i = 0; i < 4; i++) {
        int r = row0 + r0 + i;
        if (r < N_NODES) {
            __half2 h0 = __float22half2_rn(make_float2(acc[i][0], acc[i][1]));
            __half2 h1 = __float22half2_rn(make_float2(acc[i][2], acc[i][3]));
            uint2 pk = make_uint2(*(unsigned*)&h0, *(unsigned*)&h1);
            *(uint2*)&g_feat_h[r * HD + c0] = pk;
        }

        float el = acc[i][0] * al4.x + acc[i][1] * al4.y
                 + acc[i][2] * al4.z + acc[i][3] * al4.w;
        float er = acc[i][0] * ar4.x + acc[i][1] * ar4.y
                 + acc[i][2] * ar4.z + acc[i][3] * ar4.w;
        el += __shfl_xor_sync(0xffffffffu, el, 1);
        el += __shfl_xor_sync(0xffffffffu, el, 2);
        er += __shfl_xor_sync(0xffffffffu, er, 1);
        er += __shfl_xor_sync(0xffffffffu, er, 2);
        if ((tid & 3) == 0 && r < N_NODES) {
            g_el[r * HEADS + head] = el;
            g_er[r * HEADS + head] = er;
        }
    }
}

// ---------------- K5: warp-per-node aggregation (zero atomics) ---------------
__global__ void __launch_bounds__(256) k_agg(const float* __restrict__ bias,
                                             float* __restrict__ out) {
    int warp = (blockIdx.x * blockDim.x + threadIdx.x) >> 5;
    if (warp >= N_NODES) return;
    const int n    = warp;
    const int lane = threadIdx.x & 31;
    const int g    = lane >> 3;
    const int p    = lane & 7;
    const int h    = p >> 1;

    const int beg = g_start[n];
    const int end = g_start[n + 1];

    const float er_h = g_er[n * HEADS + h];

    float acc[8] = {};
    float den = 0.0f;

    for (int i = beg + g; i < end; i += 4) {
        int s = g_ssrc[i];
        float ee = __expf(lrelu(g_el[s * HEADS + h] + er_h));
        uint4 pk = *(const uint4*)&g_feat_h[s * HD + p * 8];
        float2 f0 = __half22float2(*(__half2*)&pk.x);
        float2 f1 = __half22float2(*(__half2*)&pk.y);
        float2 f2 = __half22float2(*(__half2*)&pk.z);
        float2 f3 = __half22float2(*(__half2*)&pk.w);
        acc[0] = fmaf(f0.x, ee, acc[0]);
        acc[1] = fmaf(f0.y, ee, acc[1]);
        acc[2] = fmaf(f1.x, ee, acc[2]);
        acc[3] = fmaf(f1.y, ee, acc[3]);
        acc[4] = fmaf(f2.x, ee, acc[4]);
        acc[5] = fmaf(f2.y, ee, acc[5]);
        acc[6] = fmaf(f3.x, ee, acc[6]);
        acc[7] = fmaf(f3.y, ee, acc[7]);
        den += ee;
    }

    #pragma unroll
    for (int k = 0; k < 8; k++) {
        acc[k] += __shfl_xor_sync(0xffffffffu, acc[k], 8);
        acc[k] += __shfl_xor_sync(0xffffffffu, acc[k], 16);
    }
    den += __shfl_xor_sync(0xffffffffu, den, 8);
    den += __shfl_xor_sync(0xffffffffu, den, 16);

    float inv = (den > 0.0f) ? __fdividef(0.25f, den) : 0.0f;
    #pragma unroll
    for (int k = 0; k < 8; k++) acc[k] *= inv;

    #pragma unroll
    for (int k = 0; k < 8; k++) {
        acc[k] += __shfl_xor_sync(0xffffffffu, acc[k], 2);
        acc[k] += __shfl_xor_sync(0xffffffffu, acc[k], 4);
    }

    if (lane < 2) {
        float4 o0, o1;
        #pragma unroll
        for (int k = 0; k < 8; k++) {
            int dd = lane * 8 + k;
            float bm = 0.25f * (bias[dd] + bias[HID + dd]
                              + bias[2 * HID + dd] + bias[3 * HID + dd]);
            if (k < 4) ((float*)&o0)[k] = acc[k] + bm;
            else       ((float*)&o1)[k - 4] = acc[k] + bm;
        }
        *(float4*)&out[n * HID + lane * 8]     = o0;
        *(float4*)&out[n * HID + lane * 8 + 4] = o1;
    }
}

// ---------------- launch ------------------------------------------------------
extern "C" void kernel_launch(void* const* d_in, const int* in_sizes, int n_in,
                              void* d_out, int out_size) {
    const float* features = (const float*)d_in[0];
    const float* W        = (const float*)d_in[1];
    const float* attn_l   = (const float*)d_in[2];
    const float* attn_r   = (const float*)d_in[3];
    const float* bias     = (const float*)d_in[4];
    const void*  src_raw  = d_in[5];
    const void*  dst_raw  = d_in[6];
    float* out = (float*)d_out;

    const int T = 256;

    // side stream for the independent GEMM branch (fork/join is valid inside
    // stream capture; resources are created lazily once and reused)
    static cudaStream_t s_side = 0;
    static cudaEvent_t  ev_fork = 0, ev_join = 0;
    if (!s_side) {
        cudaStreamCreateWithFlags(&s_side, cudaStreamNonBlocking);
        cudaEventCreateWithFlags(&ev_fork, cudaEventDisableTiming);
        cudaEventCreateWithFlags(&ev_join, cudaEventDisableTiming);
    }

    // fork: gemm on side stream, sort chain on main stream
    cudaEventRecord(ev_fork, 0);
    cudaStreamWaitEvent(s_side, ev_fork, 0);
    k_gemm<<<(N_NODES + BM - 1) / BM, T, 0, s_side>>>(features, W, attn_l, attn_r);
    cudaEventRecord(ev_join, s_side);

    k_zero   <<<(SCAN_BLOCKS * SCAN_ELEMS + T - 1) / T, T>>>();
    k_convert<<<(N_EDGES + T - 1) / T, T>>>(src_raw, dst_raw);
    k_scan1  <<<SCAN_BLOCKS, T>>>();
    k_scan3  <<<SCAN_BLOCKS, T>>>();
    k_fill   <<<(N_EDGES + T - 1) / T, T>>>();

    // join: aggregation needs both branches
    cudaStreamWaitEvent(0, ev_join, 0);
    k_agg    <<<(N_NODES * 32 + T - 1) / T, T>>>(bias, out);
}

// round 10
// speedup vs baseline: 1.8195x; 1.0345x over previous
#include <cuda_runtime.h>
#include <cuda_fp16.h>
#include <math_constants.h>

#define N_NODES 50000
#define N_EDGES 1600000
#define IN_DIM  128
#define HEADS   4
#define HID     16
#define HD      64              // HEADS*HID
#define NEG_SLOPE 0.2f

#define SCAN_ELEMS 1024
#define SCAN_BLOCKS ((N_NODES + SCAN_ELEMS - 1) / SCAN_ELEMS)   // 49

// ---------------- scratch (device globals; zero-init at load) ---------------
__device__ __half g_feat_h[N_NODES * HD];   // projected features, fp16
__device__ float  g_el    [N_NODES * HEADS];
__device__ float  g_er    [N_NODES * HEADS];
__device__ int    g_ssrc  [N_EDGES];        // src ids sorted by dst segment
__device__ int    g_cnt   [SCAN_BLOCKS * SCAN_ELEMS];  // histogram (padded)
__device__ int    g_part  [SCAN_BLOCKS];    // per-block sums
__device__ int    g_flag  [SCAN_BLOCKS];    // lookback flags (reset by k_fill)
__device__ int    g_start [N_NODES + 1];    // segment starts
__device__ int    g_cursor[N_NODES];        // mutable fill cursors

__device__ __forceinline__ float lrelu(float x) {
    return x > 0.0f ? x : NEG_SLOPE * x;
}

// shared probe: is the raw index array int64 or int32?
__device__ __forceinline__ bool probe_is64(const void* s_raw) {
    __shared__ int is64s;
    if (threadIdx.x == 0) is64s = 1;
    __syncthreads();
    if (threadIdx.x < 256) {
        // int32 data ⇒ upper word of these i64 reads is a random index,
        // guaranteed >= N_NODES among 256 samples.
        unsigned long long v = ((const unsigned long long*)s_raw)[threadIdx.x];
        if (v >= (unsigned long long)N_NODES) atomicExch(&is64s, 0);
    }
    __syncthreads();
    return is64s != 0;
}

// ---------------- K1: histogram of dst (direct from raw input) --------------
__global__ void k_hist(const void* d_raw) {
    const bool is64 = probe_is64(d_raw);
    int i = blockIdx.x * blockDim.x + threadIdx.x;
    if (i >= N_EDGES) return;
    int d = is64 ? (int)((const long long*)d_raw)[i] : ((const int*)d_raw)[i];
    atomicAdd(&g_cnt[d], 1);
}

// ---------------- K2: single-kernel scan (decoupled lookback, grid=49) ------
// All 49 blocks are co-resident (148 SMs) so the spin cannot deadlock.
// Also zeroes g_cnt behind itself for the next graph replay.
__global__ void __launch_bounds__(256) k_scan() {
    __shared__ int wsum[8];
    __shared__ int s_off;
    const int b = blockIdx.x, t = threadIdx.x;
    const int lane = t & 31, w = t >> 5;

    int4 v = ((const int4*)g_cnt)[b * 256 + t];
    ((int4*)g_cnt)[b * 256 + t] = make_int4(0, 0, 0, 0);  // self-clean
    int tsum = v.x + v.y + v.z + v.w;

    // block-wide inclusive scan of thread sums
    int inc = tsum;
    #pragma unroll
    for (int o = 1; o < 32; o <<= 1) {
        int x = __shfl_up_sync(0xffffffffu, inc, o);
        if (lane >= o) inc += x;
    }
    if (lane == 31) wsum[w] = inc;
    __syncthreads();
    if (t < 8) {
        int x = wsum[t];
        #pragma unroll
        for (int o = 1; o < 8; o <<= 1) {
            int y = __shfl_up_sync(0xffu, x, o);
            if (t >= o) x += y;
        }
        wsum[t] = x;
    }
    __syncthreads();
    const int blockTotal = wsum[7];

    // publish aggregate, then look back for the exclusive block offset
    if (t == 0) {
        ((volatile int*)g_part)[b] = blockTotal;
        __threadfence();
        ((volatile int*)g_flag)[b] = 1;
    }
    if (w == 0) {           // warp 0 performs the lookback
        int acc = 0;
        for (int i = lane; i < b; i += 32) {
            while (((volatile int*)g_flag)[i] == 0) { }
            acc += ((volatile int*)g_part)[i];
        }
        #pragma unroll
        for (int o = 16; o > 0; o >>= 1)
            acc += __shfl_xor_sync(0xffffffffu, acc, o);
        if (lane == 0) s_off = acc;
    }
    __syncthreads();
    const int blockOff = s_off;

    if (b == SCAN_BLOCKS - 1 && t == 0)
        g_start[N_NODES] = blockOff + blockTotal;

    int run = blockOff + (inc - tsum) + ((w > 0) ? wsum[w - 1] : 0);
    int base = b * SCAN_ELEMS + t * 4;
    #pragma unroll
    for (int k = 0; k < 4; k++) {
        int idx = base + k;
        if (idx < N_NODES) {
            g_start[idx]  = run;
            g_cursor[idx] = run;
        }
        run += ((const int*)&v)[k];
    }
}

// ---------------- K3: fill sorted edge list (reads raw inputs directly) -----
__global__ void k_fill(const void* s_raw, const void* d_raw) {
    const bool is64 = probe_is64(d_raw);
    int i = blockIdx.x * blockDim.x + threadIdx.x;
    if (i < SCAN_BLOCKS) g_flag[i] = 0;       // reset lookback flags for next replay
    if (i >= N_EDGES) return;
    int s, d;
    if (is64) {
        s = (int)((const long long*)s_raw)[i];
        d = (int)((const long long*)d_raw)[i];
    } else {
        s = ((const int*)s_raw)[i];
        d = ((const int*)d_raw)[i];
    }
    int pos = atomicAdd(&g_cursor[d], 1);
    g_ssrc[pos] = s;
}

// ---------------- K4: GEMM feat = X @ W, fused el/er + fp16 store -----------
#define BM 64
#define KC 64
#define XPAD 68

__global__ void __launch_bounds__(256) k_gemm(const float* __restrict__ X,
                                              const float* __restrict__ W,
                                              const float* __restrict__ attn_l,
                                              const float* __restrict__ attn_r) {
    __shared__ float sW [KC * HD];
    __shared__ float sXt[KC * XPAD];
    const int tid  = threadIdx.x;
    const int row0 = blockIdx.x * BM;
    const int r0   = (tid >> 4) << 2;
    const int c0   = (tid & 15) << 2;

    float acc[4][4] = {};

    for (int k0 = 0; k0 < IN_DIM; k0 += KC) {
        #pragma unroll
        for (int i = tid; i < KC * HD; i += 256) {
            int k = i >> 6, c = i & 63;
            sW[i] = W[(k0 + k) * HD + c];
        }
        #pragma unroll
        for (int i = tid; i < BM * KC; i += 256) {
            int r = i >> 6, k = i & 63;
            int gr = row0 + r;
            float v = (gr < N_NODES) ? X[gr * IN_DIM + k0 + k] : 0.0f;
            sXt[k * XPAD + r] = v;
        }
        __syncthreads();

        #pragma unroll 8
        for (int k = 0; k < KC; k++) {
            float4 xv = *(const float4*)&sXt[k * XPAD + r0];
            float4 wv = *(const float4*)&sW [k * HD   + c0];
            acc[0][0] = fmaf(xv.x, wv.x, acc[0][0]);
            acc[0][1] = fmaf(xv.x, wv.y, acc[0][1]);
            acc[0][2] = fmaf(xv.x, wv.z, acc[0][2]);
            acc[0][3] = fmaf(xv.x, wv.w, acc[0][3]);
            acc[1][0] = fmaf(xv.y, wv.x, acc[1][0]);
            acc[1][1] = fmaf(xv.y, wv.y, acc[1][1]);
            acc[1][2] = fmaf(xv.y, wv.z, acc[1][2]);
            acc[1][3] = fmaf(xv.y, wv.w, acc[1][3]);
            acc[2][0] = fmaf(xv.z, wv.x, acc[2][0]);
            acc[2][1] = fmaf(xv.z, wv.y, acc[2][1]);
            acc[2][2] = fmaf(xv.z, wv.z, acc[2][2]);
            acc[2][3] = fmaf(xv.z, wv.w, acc[2][3]);
            acc[3][0] = fmaf(xv.w, wv.x, acc[3][0]);
            acc[3][1] = fmaf(xv.w, wv.y, acc[3][1]);
            acc[3][2] = fmaf(xv.w, wv.z, acc[3][2]);
            acc[3][3] = fmaf(xv.w, wv.w, acc[3][3]);
        }
        __syncthreads();
    }

    const float4 al4 = *(const float4*)&attn_l[c0];
    const float4 ar4 = *(const float4*)&attn_r[c0];
    const int head = (tid >> 2) & 3;

    #pragma unroll
    for (int i = 0; i < 4; i++) {
        int r = row0 + r0 + i;
        if (r < N_NODES) {
            __half2 h0 = __float22half2_rn(make_float2(acc[i][0], acc[i][1]));
            __half2 h1 = __float22half2_rn(make_float2(acc[i][2], acc[i][3]));
            uint2 pk = make_uint2(*(unsigned*)&h0, *(unsigned*)&h1);
            *(uint2*)&g_feat_h[r * HD + c0] = pk;
        }

        float el = acc[i][0] * al4.x + acc[i][1] * al4.y
                 + acc[i][2] * al4.z + acc[i][3] * al4.w;
        float er = acc[i][0] * ar4.x + acc[i][1] * ar4.y
                 + acc[i][2] * ar4.z + acc[i][3] * ar4.w;
        el += __shfl_xor_sync(0xffffffffu, el, 1);
        el += __shfl_xor_sync(0xffffffffu, el, 2);
        er += __shfl_xor_sync(0xffffffffu, er, 1);
        er += __shfl_xor_sync(0xffffffffu, er, 2);
        if ((tid & 3) == 0 && r < N_NODES) {
            g_el[r * HEADS + head] = el;
            g_er[r * HEADS + head] = er;
        }
    }
}

// ---------------- K5: warp-per-node aggregation (zero atomics) ---------------
__global__ void __launch_bounds__(256) k_agg(const float* __restrict__ bias,
                                             float* __restrict__ out) {
    int warp = (blockIdx.x * blockDim.x + threadIdx.x) >> 5;
    if (warp >= N_NODES) return;
    const int n    = warp;
    const int lane = threadIdx.x & 31;
    const int g    = lane >> 3;
    const int p    = lane & 7;
    const int h    = p >> 1;

    const int beg = g_start[n];
    const int end = g_start[n + 1];

    const float er_h = g_er[n * HEADS + h];

    float acc[8] = {};
    float den = 0.0f;

    for (int i = beg + g; i < end; i += 4) {
        int s = g_ssrc[i];
        float ee = __expf(lrelu(g_el[s * HEADS + h] + er_h));
        uint4 pk = *(const uint4*)&g_feat_h[s * HD + p * 8];
        float2 f0 = __half22float2(*(__half2*)&pk.x);
        float2 f1 = __half22float2(*(__half2*)&pk.y);
        float2 f2 = __half22float2(*(__half2*)&pk.z);
        float2 f3 = __half22float2(*(__half2*)&pk.w);
        acc[0] = fmaf(f0.x, ee, acc[0]);
        acc[1] = fmaf(f0.y, ee, acc[1]);
        acc[2] = fmaf(f1.x, ee, acc[2]);
        acc[3] = fmaf(f1.y, ee, acc[3]);
        acc[4] = fmaf(f2.x, ee, acc[4]);
        acc[5] = fmaf(f2.y, ee, acc[5]);
        acc[6] = fmaf(f3.x, ee, acc[6]);
        acc[7] = fmaf(f3.y, ee, acc[7]);
        den += ee;
    }

    #pragma unroll
    for (int k = 0; k < 8; k++) {
        acc[k] += __shfl_xor_sync(0xffffffffu, acc[k], 8);
        acc[k] += __shfl_xor_sync(0xffffffffu, acc[k], 16);
    }
    den += __shfl_xor_sync(0xffffffffu, den, 8);
    den += __shfl_xor_sync(0xffffffffu, den, 16);

    float inv = (den > 0.0f) ? __fdividef(0.25f, den) : 0.0f;
    #pragma unroll
    for (int k = 0; k < 8; k++) acc[k] *= inv;

    #pragma unroll
    for (int k = 0; k < 8; k++) {
        acc[k] += __shfl_xor_sync(0xffffffffu, acc[k], 2);
        acc[k] += __shfl_xor_sync(0xffffffffu, acc[k], 4);
    }

    if (lane < 2) {
        float4 o0, o1;
        #pragma unroll
        for (int k = 0; k < 8; k++) {
            int dd = lane * 8 + k;
            float bm = 0.25f * (bias[dd] + bias[HID + dd]
                              + bias[2 * HID + dd] + bias[3 * HID + dd]);
            if (k < 4) ((float*)&o0)[k] = acc[k] + bm;
            else       ((float*)&o1)[k - 4] = acc[k] + bm;
        }
        *(float4*)&out[n * HID + lane * 8]     = o0;
        *(float4*)&out[n * HID + lane * 8 + 4] = o1;
    }
}

// ---------------- launch ------------------------------------------------------
extern "C" void kernel_launch(void* const* d_in, const int* in_sizes, int n_in,
                              void* d_out, int out_size) {
    const float* features = (const float*)d_in[0];
    const float* W        = (const float*)d_in[1];
    const float* attn_l   = (const float*)d_in[2];
    const float* attn_r   = (const float*)d_in[3];
    const float* bias     = (const float*)d_in[4];
    const void*  src_raw  = d_in[5];
    const void*  dst_raw  = d_in[6];
    float* out = (float*)d_out;

    const int T = 256;

    static cudaStream_t s_side = 0;
    static cudaEvent_t  ev_fork = 0, ev_join = 0;
    if (!s_side) {
        cudaStreamCreateWithFlags(&s_side, cudaStreamNonBlocking);
        cudaEventCreateWithFlags(&ev_fork, cudaEventDisableTiming);
        cudaEventCreateWithFlags(&ev_join, cudaEventDisableTiming);
    }

    // fork: GEMM on side stream; sort chain on main stream
    cudaEventRecord(ev_fork, 0);
    cudaStreamWaitEvent(s_side, ev_fork, 0);
    k_gemm<<<(N_NODES + BM - 1) / BM, T, 0, s_side>>>(features, W, attn_l, attn_r);
    cudaEventRecord(ev_join, s_side);

    k_hist<<<(N_EDGES + T - 1) / T, T>>>(dst_raw);
    k_scan<<<SCAN_BLOCKS, T>>>();
    k_fill<<<(N_EDGES + T - 1) / T, T>>>(src_raw, dst_raw);

    // join: aggregation needs both branches
    cudaStreamWaitEvent(0, ev_join, 0);
    k_agg<<<(N_NODES * 32 + T - 1) / T, T>>>(bias, out);
}

// round 11
// speedup vs baseline: 1.8413x; 1.0120x over previous
#include <cuda_runtime.h>
#include <cuda_fp16.h>
#include <math_constants.h>

#define N_NODES 50000
#define N_EDGES 1600000
#define IN_DIM  128
#define HEADS   4
#define HID     16
#define HD      64              // HEADS*HID
#define NEG_SLOPE 0.2f

#define SCAN_ELEMS 1024
#define SCAN_BLOCKS ((N_NODES + SCAN_ELEMS - 1) / SCAN_ELEMS)   // 49

// ---------------- scratch (device globals; zero-init at load) ---------------
__device__ __half g_feat_h[N_NODES * HD];   // projected features, fp16
__device__ float  g_el    [N_NODES * HEADS];
__device__ float  g_er    [N_NODES * HEADS];
__device__ int    g_ssrc  [N_EDGES];        // src ids sorted by dst segment
__device__ int    g_cnt   [SCAN_BLOCKS * SCAN_ELEMS];  // histogram (padded)
__device__ int    g_part  [SCAN_BLOCKS];    // per-block sums
__device__ int    g_flag  [SCAN_BLOCKS];    // lookback flags (reset by k_fill)
__device__ int    g_start [N_NODES + 1];    // segment starts
__device__ int    g_cursor[N_NODES];        // mutable fill cursors

__device__ __forceinline__ float lrelu(float x) {
    return x > 0.0f ? x : NEG_SLOPE * x;
}

// shared probe: is the raw index array int64 or int32?
__device__ __forceinline__ bool probe_is64(const void* s_raw) {
    __shared__ int is64s;
    if (threadIdx.x == 0) is64s = 1;
    __syncthreads();
    if (threadIdx.x < 256) {
        // int32 data ⇒ upper word of these i64 reads is a random index,
        // guaranteed >= N_NODES among 256 samples.
        unsigned long long v = ((const unsigned long long*)s_raw)[threadIdx.x];
        if (v >= (unsigned long long)N_NODES) atomicExch(&is64s, 0);
    }
    __syncthreads();
    return is64s != 0;
}

// ---------------- K1: histogram of dst (direct from raw input) --------------
__global__ void k_hist(const void* d_raw) {
    const bool is64 = probe_is64(d_raw);
    int i = blockIdx.x * blockDim.x + threadIdx.x;
    if (i >= N_EDGES) return;
    int d = is64 ? (int)((const long long*)d_raw)[i] : ((const int*)d_raw)[i];
    atomicAdd(&g_cnt[d], 1);
}

// ---------------- K2: single-kernel scan (decoupled lookback, grid=49) ------
// All 49 blocks are co-resident (148 SMs) so the spin cannot deadlock.
// Also zeroes g_cnt behind itself for the next graph replay.
__global__ void __launch_bounds__(256) k_scan() {
    __shared__ int wsum[8];
    __shared__ int s_off;
    const int b = blockIdx.x, t = threadIdx.x;
    const int lane = t & 31, w = t >> 5;

    int4 v = ((const int4*)g_cnt)[b * 256 + t];
    ((int4*)g_cnt)[b * 256 + t] = make_int4(0, 0, 0, 0);  // self-clean
    int tsum = v.x + v.y + v.z + v.w;

    // block-wide inclusive scan of thread sums
    int inc = tsum;
    #pragma unroll
    for (int o = 1; o < 32; o <<= 1) {
        int x = __shfl_up_sync(0xffffffffu, inc, o);
        if (lane >= o) inc += x;
    }
    if (lane == 31) wsum[w] = inc;
    __syncthreads();
    if (t < 8) {
        int x = wsum[t];
        #pragma unroll
        for (int o = 1; o < 8; o <<= 1) {
            int y = __shfl_up_sync(0xffu, x, o);
            if (t >= o) x += y;
        }
        wsum[t] = x;
    }
    __syncthreads();
    const int blockTotal = wsum[7];

    // publish aggregate, then look back for the exclusive block offset
    if (t == 0) {
        ((volatile int*)g_part)[b] = blockTotal;
        __threadfence();
        ((volatile int*)g_flag)[b] = 1;
    }
    if (w == 0) {           // warp 0 performs the lookback
        int acc = 0;
        for (int i = lane; i < b; i += 32) {
            while (((volatile int*)g_flag)[i] == 0) { }
            acc += ((volatile int*)g_part)[i];
        }
        #pragma unroll
        for (int o = 16; o > 0; o >>= 1)
            acc += __shfl_xor_sync(0xffffffffu, acc, o);
        if (lane == 0) s_off = acc;
    }
    __syncthreads();
    const int blockOff = s_off;

    if (b == SCAN_BLOCKS - 1 && t == 0)
        g_start[N_NODES] = blockOff + blockTotal;

    int run = blockOff + (inc - tsum) + ((w > 0) ? wsum[w - 1] : 0);
    int base = b * SCAN_ELEMS + t * 4;
    #pragma unroll
    for (int k = 0; k < 4; k++) {
        int idx = base + k;
        if (idx < N_NODES) {
            g_start[idx]  = run;
            g_cursor[idx] = run;
        }
        run += ((const int*)&v)[k];
    }
}

// ---------------- K3: fill sorted edge list (reads raw inputs directly) -----
__global__ void k_fill(const void* s_raw, const void* d_raw) {
    const bool is64 = probe_is64(d_raw);
    int i = blockIdx.x * blockDim.x + threadIdx.x;
    if (i < SCAN_BLOCKS) g_flag[i] = 0;       // reset lookback flags for next replay
    if (i >= N_EDGES) return;
    int s, d;
    if (is64) {
        s = (int)((const long long*)s_raw)[i];
        d = (int)((const long long*)d_raw)[i];
    } else {
        s = ((const int*)s_raw)[i];
        d = ((const int*)d_raw)[i];
    }
    int pos = atomicAdd(&g_cursor[d], 1);
    g_ssrc[pos] = s;
}

// ---------------- K4: GEMM feat = X @ W, fused el/er + fp16 store -----------
#define BM 64
#define KC 64
#define XPAD 68

__global__ void __launch_bounds__(256) k_gemm(const float* __restrict__ X,
                                              const float* __restrict__ W,
                                              const float* __restrict__ attn_l,
                                              const float* __restrict__ attn_r) {
    __shared__ float sW [KC * HD];
    __shared__ float sXt[KC * XPAD];
    const int tid  = threadIdx.x;
    const int row0 = blockIdx.x * BM;
    const int r0   = (tid >> 4) << 2;
    const int c0   = (tid & 15) << 2;

    float acc[4][4] = {};

    for (int k0 = 0; k0 < IN_DIM; k0 += KC) {
        #pragma unroll
        for (int i = tid; i < KC * HD; i += 256) {
            int k = i >> 6, c = i & 63;
            sW[i] = W[(k0 + k) * HD + c];
        }
        #pragma unroll
        for (int i = tid; i < BM * KC; i += 256) {
            int r = i >> 6, k = i & 63;
            int gr = row0 + r;
            float v = (gr < N_NODES) ? X[gr * IN_DIM + k0 + k] : 0.0f;
            sXt[k * XPAD + r] = v;
        }
        __syncthreads();

        #pragma unroll 8
        for (int k = 0; k < KC; k++) {
            float4 xv = *(const float4*)&sXt[k * XPAD + r0];
            float4 wv = *(const float4*)&sW [k * HD   + c0];
            acc[0][0] = fmaf(xv.x, wv.x, acc[0][0]);
            acc[0][1] = fmaf(xv.x, wv.y, acc[0][1]);
            acc[0][2] = fmaf(xv.x, wv.z, acc[0][2]);
            acc[0][3] = fmaf(xv.x, wv.w, acc[0][3]);
            acc[1][0] = fmaf(xv.y, wv.x, acc[1][0]);
            acc[1][1] = fmaf(xv.y, wv.y, acc[1][1]);
            acc[1][2] = fmaf(xv.y, wv.z, acc[1][2]);
            acc[1][3] = fmaf(xv.y, wv.w, acc[1][3]);
            acc[2][0] = fmaf(xv.z, wv.x, acc[2][0]);
            acc[2][1] = fmaf(xv.z, wv.y, acc[2][1]);
            acc[2][2] = fmaf(xv.z, wv.z, acc[2][2]);
            acc[2][3] = fmaf(xv.z, wv.w, acc[2][3]);
            acc[3][0] = fmaf(xv.w, wv.x, acc[3][0]);
            acc[3][1] = fmaf(xv.w, wv.y, acc[3][1]);
            acc[3][2] = fmaf(xv.w, wv.z, acc[3][2]);
            acc[3][3] = fmaf(xv.w, wv.w, acc[3][3]);
        }
        __syncthreads();
    }

    const float4 al4 = *(const float4*)&attn_l[c0];
    const float4 ar4 = *(const float4*)&attn_r[c0];
    const int head = (tid >> 2) & 3;

    #pragma unroll
    for (int i = 0; i < 4; i++) {
        int r = row0 + r0 + i;
        if (r < N_NODES) {
            __half2 h0 = __float22half2_rn(make_float2(acc[i][0], acc[i][1]));
            __half2 h1 = __float22half2_rn(make_float2(acc[i][2], acc[i][3]));
            uint2 pk = make_uint2(*(unsigned*)&h0, *(unsigned*)&h1);
            *(uint2*)&g_feat_h[r * HD + c0] = pk;
        }

        float el = acc[i][0] * al4.x + acc[i][1] * al4.y
                 + acc[i][2] * al4.z + acc[i][3] * al4.w;
        float er = acc[i][0] * ar4.x + acc[i][1] * ar4.y
                 + acc[i][2] * ar4.z + acc[i][3] * ar4.w;
        el += __shfl_xor_sync(0xffffffffu, el, 1);
        el += __shfl_xor_sync(0xffffffffu, el, 2);
        er += __shfl_xor_sync(0xffffffffu, er, 1);
        er += __shfl_xor_sync(0xffffffffu, er, 2);
        if ((tid & 3) == 0 && r < N_NODES) {
            g_el[r * HEADS + head] = el;
            g_er[r * HEADS + head] = er;
        }
    }
}

// ---------------- K5: warp-per-node aggregation (zero atomics) ---------------
__global__ void __launch_bounds__(256) k_agg(const float* __restrict__ bias,
                                             float* __restrict__ out) {
    int warp = (blockIdx.x * blockDim.x + threadIdx.x) >> 5;
    if (warp >= N_NODES) return;
    const int n    = warp;
    const int lane = threadIdx.x & 31;
    const int g    = lane >> 3;
    const int p    = lane & 7;
    const int h    = p >> 1;

    const int beg = g_start[n];
    const int end = g_start[n + 1];

    const float er_h = g_er[n * HEADS + h];

    float acc[8] = {};
    float den = 0.0f;

    for (int i = beg + g; i < end; i += 4) {
        int s = g_ssrc[i];
        float ee = __expf(lrelu(g_el[s * HEADS + h] + er_h));
        uint4 pk = *(const uint4*)&g_feat_h[s * HD + p * 8];
        float2 f0 = __half22float2(*(__half2*)&pk.x);
        float2 f1 = __half22float2(*(__half2*)&pk.y);
        float2 f2 = __half22float2(*(__half2*)&pk.z);
        float2 f3 = __half22float2(*(__half2*)&pk.w);
        acc[0] = fmaf(f0.x, ee, acc[0]);
        acc[1] = fmaf(f0.y, ee, acc[1]);
        acc[2] = fmaf(f1.x, ee, acc[2]);
        acc[3] = fmaf(f1.y, ee, acc[3]);
        acc[4] = fmaf(f2.x, ee, acc[4]);
        acc[5] = fmaf(f2.y, ee, acc[5]);
        acc[6] = fmaf(f3.x, ee, acc[6]);
        acc[7] = fmaf(f3.y, ee, acc[7]);
        den += ee;
    }

    #pragma unroll
    for (int k = 0; k < 8; k++) {
        acc[k] += __shfl_xor_sync(0xffffffffu, acc[k], 8);
        acc[k] += __shfl_xor_sync(0xffffffffu, acc[k], 16);
    }
    den += __shfl_xor_sync(0xffffffffu, den, 8);
    den += __shfl_xor_sync(0xffffffffu, den, 16);

    float inv = (den > 0.0f) ? __fdividef(0.25f, den) : 0.0f;
    #pragma unroll
    for (int k = 0; k < 8; k++) acc[k] *= inv;

    #pragma unroll
    for (int k = 0; k < 8; k++) {
        acc[k] += __shfl_xor_sync(0xffffffffu, acc[k], 2);
        acc[k] += __shfl_xor_sync(0xffffffffu, acc[k], 4);
    }

    if (lane < 2) {
        float4 o0, o1;
        #pragma unroll
        for (int k = 0; k < 8; k++) {
            int dd = lane * 8 + k;
            float bm = 0.25f * (bias[dd] + bias[HID + dd]
                              + bias[2 * HID + dd] + bias[3 * HID + dd]);
            if (k < 4) ((float*)&o0)[k] = acc[k] + bm;
            else       ((float*)&o1)[k - 4] = acc[k] + bm;
        }
        *(float4*)&out[n * HID + lane * 8]     = o0;
        *(float4*)&out[n * HID + lane * 8 + 4] = o1;
    }
}

// ---------------- launch ------------------------------------------------------
extern "C" void kernel_launch(void* const* d_in, const int* in_sizes, int n_in,
                              void* d_out, int out_size) {
    const float* features = (const float*)d_in[0];
    const float* W        = (const float*)d_in[1];
    const float* attn_l   = (const float*)d_in[2];
    const float* attn_r   = (const float*)d_in[3];
    const float* bias     = (const float*)d_in[4];
    const void*  src_raw  = d_in[5];
    const void*  dst_raw  = d_in[6];
    float* out = (float*)d_out;

    const int T = 256;

    static cudaStream_t s_side = 0;
    static cudaEvent_t  ev_fork = 0, ev_join = 0;
    if (!s_side) {
        cudaStreamCreateWithFlags(&s_side, cudaStreamNonBlocking);
        cudaEventCreateWithFlags(&ev_fork, cudaEventDisableTiming);
        cudaEventCreateWithFlags(&ev_join, cudaEventDisableTiming);
    }

    // fork: GEMM on side stream; sort chain on main stream
    cudaEventRecord(ev_fork, 0);
    cudaStreamWaitEvent(s_side, ev_fork, 0);
    k_gemm<<<(N_NODES + BM - 1) / BM, T, 0, s_side>>>(features, W, attn_l, attn_r);
    cudaEventRecord(ev_join, s_side);

    k_hist<<<(N_EDGES + T - 1) / T, T>>>(dst_raw);
    k_scan<<<SCAN_BLOCKS, T>>>();
    k_fill<<<(N_EDGES + T - 1) / T, T>>>(src_raw, dst_raw);

    // join: aggregation needs both branches
    cudaStreamWaitEvent(0, ev_join, 0);
    k_agg<<<(N_NODES * 32 + T - 1) / T, T>>>(bias, out);
}

// round 12
// speedup vs baseline: 1.8425x; 1.0006x over previous
#include <cuda_runtime.h>
#include <cuda_fp16.h>
#include <math_constants.h>

#define N_NODES 50000
#define N_EDGES 1600000
#define IN_DIM  128
#define HEADS   4
#define HID     16
#define HD      64              // HEADS*HID
#define NEG_SLOPE 0.2f

#define SCAN_ELEMS 1024
#define SCAN_BLOCKS ((N_NODES + SCAN_ELEMS - 1) / SCAN_ELEMS)   // 49

// ---------------- scratch (device globals; zero-init at load) ---------------
__device__ __half g_feat_h[N_NODES * HD];   // projected features, fp16
__device__ float  g_el    [N_NODES * HEADS];
__device__ float  g_er    [N_NODES * HEADS];
__device__ int    g_ssrc  [N_EDGES];        // src ids sorted by dst segment
__device__ int    g_cnt   [SCAN_BLOCKS * SCAN_ELEMS];  // histogram (padded)
__device__ int    g_part  [SCAN_BLOCKS];    // per-block sums
__device__ int    g_flag  [SCAN_BLOCKS];    // lookback flags (reset by k_fill)
__device__ int    g_start [N_NODES + 1];    // segment starts
__device__ int    g_cursor[N_NODES];        // mutable fill cursors

__device__ __forceinline__ float lrelu(float x) {
    return x > 0.0f ? x : NEG_SLOPE * x;
}

// shared probe: is the raw index array int64 or int32?
__device__ __forceinline__ bool probe_is64(const void* s_raw) {
    __shared__ int is64s;
    if (threadIdx.x == 0) is64s = 1;
    __syncthreads();
    if (threadIdx.x < 256) {
        // int32 data ⇒ upper word of these i64 reads is a random index,
        // guaranteed >= N_NODES among 256 samples.
        unsigned long long v = ((const unsigned long long*)s_raw)[threadIdx.x];
        if (v >= (unsigned long long)N_NODES) atomicExch(&is64s, 0);
    }
    __syncthreads();
    return is64s != 0;
}

// load 4 consecutive edge indices starting at e (e % 4 == 0)
__device__ __forceinline__ void load4_idx(const void* raw, bool is64, int e, int* v) {
    if (is64) {
        longlong2 a = ((const longlong2*)raw)[e >> 1];
        longlong2 b = ((const longlong2*)raw)[(e >> 1) + 1];
        v[0] = (int)a.x; v[1] = (int)a.y; v[2] = (int)b.x; v[3] = (int)b.y;
    } else {
        int4 a = ((const int4*)raw)[e >> 2];
        v[0] = a.x; v[1] = a.y; v[2] = a.z; v[3] = a.w;
    }
}

// ---------------- K1: histogram of dst, 4 edges / thread --------------------
__global__ void k_hist(const void* d_raw) {
    const bool is64 = probe_is64(d_raw);
    int e = (blockIdx.x * blockDim.x + threadIdx.x) * 4;
    if (e >= N_EDGES) return;
    int d[4];
    load4_idx(d_raw, is64, e, d);
    #pragma unroll
    for (int k = 0; k < 4; k++) atomicAdd(&g_cnt[d[k]], 1);
}

// ---------------- K2: single-kernel scan (decoupled lookback, grid=49) ------
__global__ void __launch_bounds__(256) k_scan() {
    __shared__ int wsum[8];
    __shared__ int s_off;
    const int b = blockIdx.x, t = threadIdx.x;
    const int lane = t & 31, w = t >> 5;

    int4 v = ((const int4*)g_cnt)[b * 256 + t];
    ((int4*)g_cnt)[b * 256 + t] = make_int4(0, 0, 0, 0);  // self-clean
    int tsum = v.x + v.y + v.z + v.w;

    int inc = tsum;
    #pragma unroll
    for (int o = 1; o < 32; o <<= 1) {
        int x = __shfl_up_sync(0xffffffffu, inc, o);
        if (lane >= o) inc += x;
    }
    if (lane == 31) wsum[w] = inc;
    __syncthreads();
    if (t < 8) {
        int x = wsum[t];
        #pragma unroll
        for (int o = 1; o < 8; o <<= 1) {
            int y = __shfl_up_sync(0xffu, x, o);
            if (t >= o) x += y;
        }
        wsum[t] = x;
    }
    __syncthreads();
    const int blockTotal = wsum[7];

    if (t == 0) {
        ((volatile int*)g_part)[b] = blockTotal;
        __threadfence();
        ((volatile int*)g_flag)[b] = 1;
    }
    if (w == 0) {
        int acc = 0;
        for (int i = lane; i < b; i += 32) {
            while (((volatile int*)g_flag)[i] == 0) { }
            acc += ((volatile int*)g_part)[i];
        }
        #pragma unroll
        for (int o = 16; o > 0; o >>= 1)
            acc += __shfl_xor_sync(0xffffffffu, acc, o);
        if (lane == 0) s_off = acc;
    }
    __syncthreads();
    const int blockOff = s_off;

    if (b == SCAN_BLOCKS - 1 && t == 0)
        g_start[N_NODES] = blockOff + blockTotal;

    int run = blockOff + (inc - tsum) + ((w > 0) ? wsum[w - 1] : 0);
    int base = b * SCAN_ELEMS + t * 4;
    #pragma unroll
    for (int k = 0; k < 4; k++) {
        int idx = base + k;
        if (idx < N_NODES) {
            g_start[idx]  = run;
            g_cursor[idx] = run;
        }
        run += ((const int*)&v)[k];
    }
}

// ---------------- K3: fill sorted edge list, 4 edges / thread ----------------
__global__ void k_fill(const void* s_raw, const void* d_raw) {
    const bool is64 = probe_is64(d_raw);
    int tidg = blockIdx.x * blockDim.x + threadIdx.x;
    if (tidg < SCAN_BLOCKS) g_flag[tidg] = 0;   // reset lookback flags
    int e = tidg * 4;
    if (e >= N_EDGES) return;
    int s[4], d[4];
    load4_idx(s_raw, is64, e, s);
    load4_idx(d_raw, is64, e, d);
    int pos[4];
    #pragma unroll
    for (int k = 0; k < 4; k++) pos[k] = atomicAdd(&g_cursor[d[k]], 1);
    #pragma unroll
    for (int k = 0; k < 4; k++) g_ssrc[pos[k]] = s[k];
}

// ---------------- K4: GEMM feat = X @ W, fused el/er + fp16 store -----------
#define BM 64
#define KC 64
#define XPAD 68

__global__ void __launch_bounds__(256) k_gemm(const float* __restrict__ X,
                                              const float* __restrict__ W,
                                              const float* __restrict__ attn_l,
                                              const float* __restrict__ attn_r) {
    __shared__ float sW [KC * HD];
    __shared__ float sXt[KC * XPAD];
    const int tid  = threadIdx.x;
    const int row0 = blockIdx.x * BM;
    const int r0   = (tid >> 4) << 2;
    const int c0   = (tid & 15) << 2;

    float acc[4][4] = {};

    for (int k0 = 0; k0 < IN_DIM; k0 += KC) {
        #pragma unroll
        for (int i = tid; i < KC * HD; i += 256) {
            int k = i >> 6, c = i & 63;
            sW[i] = W[(k0 + k) * HD + c];
        }
        #pragma unroll
        for (int i = tid; i < BM * KC; i += 256) {
            int r = i >> 6, k = i & 63;
            int gr = row0 + r;
            float v = (gr < N_NODES) ? X[gr * IN_DIM + k0 + k] : 0.0f;
            sXt[k * XPAD + r] = v;
        }
        __syncthreads();

        #pragma unroll 8
        for (int k = 0; k < KC; k++) {
            float4 xv = *(const float4*)&sXt[k * XPAD + r0];
            float4 wv = *(const float4*)&sW [k * HD   + c0];
            acc[0][0] = fmaf(xv.x, wv.x, acc[0][0]);
            acc[0][1] = fmaf(xv.x, wv.y, acc[0][1]);
            acc[0][2] = fmaf(xv.x, wv.z, acc[0][2]);
            acc[0][3] = fmaf(xv.x, wv.w, acc[0][3]);
            acc[1][0] = fmaf(xv.y, wv.x, acc[1][0]);
            acc[1][1] = fmaf(xv.y, wv.y, acc[1][1]);
            acc[1][2] = fmaf(xv.y, wv.z, acc[1][2]);
            acc[1][3] = fmaf(xv.y, wv.w, acc[1][3]);
            acc[2][0] = fmaf(xv.z, wv.x, acc[2][0]);
            acc[2][1] = fmaf(xv.z, wv.y, acc[2][1]);
            acc[2][2] = fmaf(xv.z, wv.z, acc[2][2]);
            acc[2][3] = fmaf(xv.z, wv.w, acc[2][3]);
            acc[3][0] = fmaf(xv.w, wv.x, acc[3][0]);
            acc[3][1] = fmaf(xv.w, wv.y, acc[3][1]);
            acc[3][2] = fmaf(xv.w, wv.z, acc[3][2]);
            acc[3][3] = fmaf(xv.w, wv.w, acc[3][3]);
        }
        __syncthreads();
    }

    const float4 al4 = *(const float4*)&attn_l[c0];
    const float4 ar4 = *(const float4*)&attn_r[c0];
    const int head = (tid >> 2) & 3;

    #pragma unroll
    for (int i = 0; i < 4; i++) {
        int r = row0 + r0 + i;
        if (r < N_NODES) {
            __half2 h0 = __float22half2_rn(make_float2(acc[i][0], acc[i][1]));
            __half2 h1 = __float22half2_rn(make_float2(acc[i][2], acc[i][3]));
            uint2 pk = make_uint2(*(unsigned*)&h0, *(unsigned*)&h1);
            *(uint2*)&g_feat_h[r * HD + c0] = pk;
        }

        float el = acc[i][0] * al4.x + acc[i][1] * al4.y
                 + acc[i][2] * al4.z + acc[i][3] * al4.w;
        float er = acc[i][0] * ar4.x + acc[i][1] * ar4.y
                 + acc[i][2] * ar4.z + acc[i][3] * ar4.w;
        el += __shfl_xor_sync(0xffffffffu, el, 1);
        el += __shfl_xor_sync(0xffffffffu, el, 2);
        er += __shfl_xor_sync(0xffffffffu, er, 1);
        er += __shfl_xor_sync(0xffffffffu, er, 2);
        if ((tid & 3) == 0 && r < N_NODES) {
            g_el[r * HEADS + head] = el;
            g_er[r * HEADS + head] = er;
        }
    }
}

// ---------------- K5: warp-per-node aggregation, 2 edges in flight ----------
__global__ void __launch_bounds__(256) k_agg(const float* __restrict__ bias,
                                             float* __restrict__ out) {
    int warp = (blockIdx.x * blockDim.x + threadIdx.x) >> 5;
    if (warp >= N_NODES) return;
    const int n    = warp;
    const int lane = threadIdx.x & 31;
    const int g    = lane >> 3;
    const int p    = lane & 7;
    const int h    = p >> 1;

    const int beg = g_start[n];
    const int end = g_start[n + 1];

    const float er_h = g_er[n * HEADS + h];

    float acc[8] = {};
    float den = 0.0f;

    int i = beg + g;
    // unroll-2: two edges per group in flight (stride 4 per group, 8 total)
    for (; i + 4 < end; i += 8) {
        int s0 = g_ssrc[i];
        int s1 = g_ssrc[i + 4];
        float l0 = g_el[s0 * HEADS + h];
        float l1 = g_el[s1 * HEADS + h];
        uint4 pk0 = *(const uint4*)&g_feat_h[s0 * HD + p * 8];
        uint4 pk1 = *(const uint4*)&g_feat_h[s1 * HD + p * 8];
        float ee0 = __expf(lrelu(l0 + er_h));
        float ee1 = __expf(lrelu(l1 + er_h));
        float2 a0 = __half22float2(*(__half2*)&pk0.x);
        float2 a1 = __half22float2(*(__half2*)&pk0.y);
        float2 a2 = __half22float2(*(__half2*)&pk0.z);
        float2 a3 = __half22float2(*(__half2*)&pk0.w);
        float2 b0 = __half22float2(*(__half2*)&pk1.x);
        float2 b1 = __half22float2(*(__half2*)&pk1.y);
        float2 b2 = __half22float2(*(__half2*)&pk1.z);
        float2 b3 = __half22float2(*(__half2*)&pk1.w);
        acc[0] = fmaf(a0.x, ee0, fmaf(b0.x, ee1, acc[0]));
        acc[1] = fmaf(a0.y, ee0, fmaf(b0.y, ee1, acc[1]));
        acc[2] = fmaf(a1.x, ee0, fmaf(b1.x, ee1, acc[2]));
        acc[3] = fmaf(a1.y, ee0, fmaf(b1.y, ee1, acc[3]));
        acc[4] = fmaf(a2.x, ee0, fmaf(b2.x, ee1, acc[4]));
        acc[5] = fmaf(a2.y, ee0, fmaf(b2.y, ee1, acc[5]));
        acc[6] = fmaf(a3.x, ee0, fmaf(b3.x, ee1, acc[6]));
        acc[7] = fmaf(a3.y, ee0, fmaf(b3.y, ee1, acc[7]));
        den += ee0 + ee1;
    }
    if (i < end) {
        int s = g_ssrc[i];
        float ee = __expf(lrelu(g_el[s * HEADS + h] + er_h));
        uint4 pk = *(const uint4*)&g_feat_h[s * HD + p * 8];
        float2 f0 = __half22float2(*(__half2*)&pk.x);
        float2 f1 = __half22float2(*(__half2*)&pk.y);
        float2 f2 = __half22float2(*(__half2*)&pk.z);
        float2 f3 = __half22float2(*(__half2*)&pk.w);
        acc[0] = fmaf(f0.x, ee, acc[0]);
        acc[1] = fmaf(f0.y, ee, acc[1]);
        acc[2] = fmaf(f1.x, ee, acc[2]);
        acc[3] = fmaf(f1.y, ee, acc[3]);
        acc[4] = fmaf(f2.x, ee, acc[4]);
        acc[5] = fmaf(f2.y, ee, acc[5]);
        acc[6] = fmaf(f3.x, ee, acc[6]);
        acc[7] = fmaf(f3.y, ee, acc[7]);
        den += ee;
    }

    #pragma unroll
    for (int k = 0; k < 8; k++) {
        acc[k] += __shfl_xor_sync(0xffffffffu, acc[k], 8);
        acc[k] += __shfl_xor_sync(0xffffffffu, acc[k], 16);
    }
    den += __shfl_xor_sync(0xffffffffu, den, 8);
    den += __shfl_xor_sync(0xffffffffu, den, 16);

    float inv = (den > 0.0f) ? __fdividef(0.25f, den) : 0.0f;
    #pragma unroll
    for (int k = 0; k < 8; k++) acc[k] *= inv;

    #pragma unroll
    for (int k = 0; k < 8; k++) {
        acc[k] += __shfl_xor_sync(0xffffffffu, acc[k], 2);
        acc[k] += __shfl_xor_sync(0xffffffffu, acc[k], 4);
    }

    if (lane < 2) {
        float4 o0, o1;
        #pragma unroll
        for (int k = 0; k < 8; k++) {
            int dd = lane * 8 + k;
            float bm = 0.25f * (bias[dd] + bias[HID + dd]
                              + bias[2 * HID + dd] + bias[3 * HID + dd]);
            if (k < 4) ((float*)&o0)[k] = acc[k] + bm;
            else       ((float*)&o1)[k - 4] = acc[k] + bm;
        }
        *(float4*)&out[n * HID + lane * 8]     = o0;
        *(float4*)&out[n * HID + lane * 8 + 4] = o1;
    }
}

// ---------------- launch ------------------------------------------------------
extern "C" void kernel_launch(void* const* d_in, const int* in_sizes, int n_in,
                              void* d_out, int out_size) {
    const float* features = (const float*)d_in[0];
    const float* W        = (const float*)d_in[1];
    const float* attn_l   = (const float*)d_in[2];
    const float* attn_r   = (const float*)d_in[3];
    const float* bias     = (const float*)d_in[4];
    const void*  src_raw  = d_in[5];
    const void*  dst_raw  = d_in[6];
    float* out = (float*)d_out;

    const int T = 256;

    static cudaStream_t s_side = 0;
    static cudaEvent_t  ev_fork = 0, ev_join = 0;
    if (!s_side) {
        cudaStreamCreateWithFlags(&s_side, cudaStreamNonBlocking);
        cudaEventCreateWithFlags(&ev_fork, cudaEventDisableTiming);
        cudaEventCreateWithFlags(&ev_join, cudaEventDisableTiming);
    }

    // fork: GEMM on side stream; sort chain on main stream
    cudaEventRecord(ev_fork, 0);
    cudaStreamWaitEvent(s_side, ev_fork, 0);
    k_gemm<<<(N_NODES + BM - 1) / BM, T, 0, s_side>>>(features, W, attn_l, attn_r);
    cudaEventRecord(ev_join, s_side);

    k_hist<<<(N_EDGES / 4 + T - 1) / T, T>>>(dst_raw);
    k_scan<<<SCAN_BLOCKS, T>>>();
    k_fill<<<(N_EDGES / 4 + T - 1) / T, T>>>(src_raw, dst_raw);

    // join: aggregation needs both branches
    cudaStreamWaitEvent(0, ev_join, 0);
    k_agg<<<(N_NODES * 32 + T - 1) / T, T>>>(bias, out);
}

// round 13
// speedup vs baseline: 1.8691x; 1.0144x over previous
#include <cuda_runtime.h>
#include <cuda_fp16.h>
#include <math_constants.h>

#define N_NODES 50000
#define N_EDGES 1600000
#define IN_DIM  128
#define HEADS   4
#define HID     16
#define HD      64              // HEADS*HID
#define NEG_SLOPE 0.2f

#define SCAN_ELEMS 1024
#define SCAN_BLOCKS ((N_NODES + SCAN_ELEMS - 1) / SCAN_ELEMS)   // 49

// ---------------- scratch (device globals; zero-init at load) ---------------
__device__ __half g_feat_h[N_NODES * HD];   // projected features, fp16
__device__ float  g_el    [N_NODES * HEADS];
__device__ float  g_er    [N_NODES * HEADS];
__device__ int    g_ssrc  [N_EDGES];        // src ids sorted by dst segment
__device__ int    g_rank  [N_EDGES];        // rank of edge within its dst bucket
__device__ int    g_cnt   [SCAN_BLOCKS * SCAN_ELEMS];  // histogram (padded)
__device__ int    g_part  [SCAN_BLOCKS];    // per-block sums
__device__ int    g_flag  [SCAN_BLOCKS];    // lookback flags (reset by k_fill)
__device__ int    g_start [N_NODES + 1];    // segment starts

__device__ __forceinline__ float lrelu(float x) {
    return x > 0.0f ? x : NEG_SLOPE * x;
}

// shared probe: is the raw index array int64 or int32?
__device__ __forceinline__ bool probe_is64(const void* s_raw) {
    __shared__ int is64s;
    if (threadIdx.x == 0) is64s = 1;
    __syncthreads();
    if (threadIdx.x < 256) {
        // int32 data ⇒ upper word of these i64 reads is a random index,
        // guaranteed >= N_NODES among 256 samples.
        unsigned long long v = ((const unsigned long long*)s_raw)[threadIdx.x];
        if (v >= (unsigned long long)N_NODES) atomicExch(&is64s, 0);
    }
    __syncthreads();
    return is64s != 0;
}

// load 4 consecutive edge indices starting at e (e % 4 == 0)
__device__ __forceinline__ void load4_idx(const void* raw, bool is64, int e, int* v) {
    if (is64) {
        longlong2 a = ((const longlong2*)raw)[e >> 1];
        longlong2 b = ((const longlong2*)raw)[(e >> 1) + 1];
        v[0] = (int)a.x; v[1] = (int)a.y; v[2] = (int)b.x; v[3] = (int)b.y;
    } else {
        int4 a = ((const int4*)raw)[e >> 2];
        v[0] = a.x; v[1] = a.y; v[2] = a.z; v[3] = a.w;
    }
}

// ---------------- K1: histogram of dst + record per-edge rank ---------------
__global__ void k_hist(const void* d_raw) {
    const bool is64 = probe_is64(d_raw);
    int e = (blockIdx.x * blockDim.x + threadIdx.x) * 4;
    if (e >= N_EDGES) return;
    int d[4];
    load4_idx(d_raw, is64, e, d);
    int4 r;
    r.x = atomicAdd(&g_cnt[d[0]], 1);
    r.y = atomicAdd(&g_cnt[d[1]], 1);
    r.z = atomicAdd(&g_cnt[d[2]], 1);
    r.w = atomicAdd(&g_cnt[d[3]], 1);
    ((int4*)g_rank)[e >> 2] = r;            // coalesced
}

// ---------------- K2: single-kernel scan (decoupled lookback, grid=49) ------
__global__ void __launch_bounds__(256) k_scan() {
    __shared__ int wsum[8];
    __shared__ int s_off;
    const int b = blockIdx.x, t = threadIdx.x;
    const int lane = t & 31, w = t >> 5;

    int4 v = ((const int4*)g_cnt)[b * 256 + t];
    ((int4*)g_cnt)[b * 256 + t] = make_int4(0, 0, 0, 0);  // self-clean
    int tsum = v.x + v.y + v.z + v.w;

    int inc = tsum;
    #pragma unroll
    for (int o = 1; o < 32; o <<= 1) {
        int x = __shfl_up_sync(0xffffffffu, inc, o);
        if (lane >= o) inc += x;
    }
    if (lane == 31) wsum[w] = inc;
    __syncthreads();
    if (t < 8) {
        int x = wsum[t];
        #pragma unroll
        for (int o = 1; o < 8; o <<= 1) {
            int y = __shfl_up_sync(0xffu, x, o);
            if (t >= o) x += y;
        }
        wsum[t] = x;
    }
    __syncthreads();
    const int blockTotal = wsum[7];

    if (t == 0) {
        ((volatile int*)g_part)[b] = blockTotal;
        __threadfence();
        ((volatile int*)g_flag)[b] = 1;
    }
    if (w == 0) {
        int acc = 0;
        for (int i = lane; i < b; i += 32) {
            while (((volatile int*)g_flag)[i] == 0) { }
            acc += ((volatile int*)g_part)[i];
        }
        #pragma unroll
        for (int o = 16; o > 0; o >>= 1)
            acc += __shfl_xor_sync(0xffffffffu, acc, o);
        if (lane == 0) s_off = acc;
    }
    __syncthreads();
    const int blockOff = s_off;

    if (b == SCAN_BLOCKS - 1 && t == 0)
        g_start[N_NODES] = blockOff + blockTotal;

    int run = blockOff + (inc - tsum) + ((w > 0) ? wsum[w - 1] : 0);
    int base = b * SCAN_ELEMS + t * 4;
    #pragma unroll
    for (int k = 0; k < 4; k++) {
        int idx = base + k;
        if (idx < N_NODES) g_start[idx] = run;
        run += ((const int*)&v)[k];
    }
}

// ---------------- K3: fill sorted edge list — NO atomics --------------------
__global__ void k_fill(const void* s_raw, const void* d_raw) {
    const bool is64 = probe_is64(d_raw);
    int tidg = blockIdx.x * blockDim.x + threadIdx.x;
    if (tidg < SCAN_BLOCKS) g_flag[tidg] = 0;   // reset lookback flags
    int e = tidg * 4;
    if (e >= N_EDGES) return;
    int s[4], d[4];
    load4_idx(s_raw, is64, e, s);
    load4_idx(d_raw, is64, e, d);
    int4 r = ((const int4*)g_rank)[e >> 2];
    // four independent gathers of segment starts (L2-resident, 200 KB)
    int p0 = g_start[d[0]] + r.x;
    int p1 = g_start[d[1]] + r.y;
    int p2 = g_start[d[2]] + r.z;
    int p3 = g_start[d[3]] + r.w;
    g_ssrc[p0] = s[0];
    g_ssrc[p1] = s[1];
    g_ssrc[p2] = s[2];
    g_ssrc[p3] = s[3];
}

// ---------------- K4: GEMM feat = X @ W, fused el/er + fp16 store -----------
#define BM 64
#define KC 64
#define XPAD 68

__global__ void __launch_bounds__(256) k_gemm(const float* __restrict__ X,
                                              const float* __restrict__ W,
                                              const float* __restrict__ attn_l,
                                              const float* __restrict__ attn_r) {
    __shared__ float sW [KC * HD];
    __shared__ float sXt[KC * XPAD];
    const int tid  = threadIdx.x;
    const int row0 = blockIdx.x * BM;
    const int r0   = (tid >> 4) << 2;
    const int c0   = (tid & 15) << 2;

    float acc[4][4] = {};

    for (int k0 = 0; k0 < IN_DIM; k0 += KC) {
        #pragma unroll
        for (int i = tid; i < KC * HD; i += 256) {
            int k = i >> 6, c = i & 63;
            sW[i] = W[(k0 + k) * HD + c];
        }
        #pragma unroll
        for (int i = tid; i < BM * KC; i += 256) {
            int r = i >> 6, k = i & 63;
            int gr = row0 + r;
            float v = (gr < N_NODES) ? X[gr * IN_DIM + k0 + k] : 0.0f;
            sXt[k * XPAD + r] = v;
        }
        __syncthreads();

        #pragma unroll 8
        for (int k = 0; k < KC; k++) {
            float4 xv = *(const float4*)&sXt[k * XPAD + r0];
            float4 wv = *(const float4*)&sW [k * HD   + c0];
            acc[0][0] = fmaf(xv.x, wv.x, acc[0][0]);
            acc[0][1] = fmaf(xv.x, wv.y, acc[0][1]);
            acc[0][2] = fmaf(xv.x, wv.z, acc[0][2]);
            acc[0][3] = fmaf(xv.x, wv.w, acc[0][3]);
            acc[1][0] = fmaf(xv.y, wv.x, acc[1][0]);
            acc[1][1] = fmaf(xv.y, wv.y, acc[1][1]);
            acc[1][2] = fmaf(xv.y, wv.z, acc[1][2]);
            acc[1][3] = fmaf(xv.y, wv.w, acc[1][3]);
            acc[2][0] = fmaf(xv.z, wv.x, acc[2][0]);
            acc[2][1] = fmaf(xv.z, wv.y, acc[2][1]);
            acc[2][2] = fmaf(xv.z, wv.z, acc[2][2]);
            acc[2][3] = fmaf(xv.z, wv.w, acc[2][3]);
            acc[3][0] = fmaf(xv.w, wv.x, acc[3][0]);
            acc[3][1] = fmaf(xv.w, wv.y, acc[3][1]);
            acc[3][2] = fmaf(xv.w, wv.z, acc[3][2]);
            acc[3][3] = fmaf(xv.w, wv.w, acc[3][3]);
        }
        __syncthreads();
    }

    const float4 al4 = *(const float4*)&attn_l[c0];
    const float4 ar4 = *(const float4*)&attn_r[c0];
    const int head = (tid >> 2) & 3;

    #pragma unroll
    for (int i = 0; i < 4; i++) {
        int r = row0 + r0 + i;
        if (r < N_NODES) {
            __half2 h0 = __float22half2_rn(make_float2(acc[i][0], acc[i][1]));
            __half2 h1 = __float22half2_rn(make_float2(acc[i][2], acc[i][3]));
            uint2 pk = make_uint2(*(unsigned*)&h0, *(unsigned*)&h1);
            *(uint2*)&g_feat_h[r * HD + c0] = pk;
        }

        float el = acc[i][0] * al4.x + acc[i][1] * al4.y
                 + acc[i][2] * al4.z + acc[i][3] * al4.w;
        float er = acc[i][0] * ar4.x + acc[i][1] * ar4.y
                 + acc[i][2] * ar4.z + acc[i][3] * ar4.w;
        el += __shfl_xor_sync(0xffffffffu, el, 1);
        el += __shfl_xor_sync(0xffffffffu, el, 2);
        er += __shfl_xor_sync(0xffffffffu, er, 1);
        er += __shfl_xor_sync(0xffffffffu, er, 2);
        if ((tid & 3) == 0 && r < N_NODES) {
            g_el[r * HEADS + head] = el;
            g_er[r * HEADS + head] = er;
        }
    }
}

// ---------------- K5: warp-per-node aggregation, 2 edges in flight ----------
__global__ void __launch_bounds__(256) k_agg(const float* __restrict__ bias,
                                             float* __restrict__ out) {
    int warp = (blockIdx.x * blockDim.x + threadIdx.x) >> 5;
    if (warp >= N_NODES) return;
    const int n    = warp;
    const int lane = threadIdx.x & 31;
    const int g    = lane >> 3;
    const int p    = lane & 7;
    const int h    = p >> 1;

    const int beg = g_start[n];
    const int end = g_start[n + 1];

    const float er_h = g_er[n * HEADS + h];

    float acc[8] = {};
    float den = 0.0f;

    int i = beg + g;
    for (; i + 4 < end; i += 8) {
        int s0 = g_ssrc[i];
        int s1 = g_ssrc[i + 4];
        float l0 = g_el[s0 * HEADS + h];
        float l1 = g_el[s1 * HEADS + h];
        uint4 pk0 = *(const uint4*)&g_feat_h[s0 * HD + p * 8];
        uint4 pk1 = *(const uint4*)&g_feat_h[s1 * HD + p * 8];
        float ee0 = __expf(lrelu(l0 + er_h));
        float ee1 = __expf(lrelu(l1 + er_h));
        float2 a0 = __half22float2(*(__half2*)&pk0.x);
        float2 a1 = __half22float2(*(__half2*)&pk0.y);
        float2 a2 = __half22float2(*(__half2*)&pk0.z);
        float2 a3 = __half22float2(*(__half2*)&pk0.w);
        float2 b0 = __half22float2(*(__half2*)&pk1.x);
        float2 b1 = __half22float2(*(__half2*)&pk1.y);
        float2 b2 = __half22float2(*(__half2*)&pk1.z);
        float2 b3 = __half22float2(*(__half2*)&pk1.w);
        acc[0] = fmaf(a0.x, ee0, fmaf(b0.x, ee1, acc[0]));
        acc[1] = fmaf(a0.y, ee0, fmaf(b0.y, ee1, acc[1]));
        acc[2] = fmaf(a1.x, ee0, fmaf(b1.x, ee1, acc[2]));
        acc[3] = fmaf(a1.y, ee0, fmaf(b1.y, ee1, acc[3]));
        acc[4] = fmaf(a2.x, ee0, fmaf(b2.x, ee1, acc[4]));
        acc[5] = fmaf(a2.y, ee0, fmaf(b2.y, ee1, acc[5]));
        acc[6] = fmaf(a3.x, ee0, fmaf(b3.x, ee1, acc[6]));
        acc[7] = fmaf(a3.y, ee0, fmaf(b3.y, ee1, acc[7]));
        den += ee0 + ee1;
    }
    if (i < end) {
        int s = g_ssrc[i];
        float ee = __expf(lrelu(g_el[s * HEADS + h] + er_h));
        uint4 pk = *(const uint4*)&g_feat_h[s * HD + p * 8];
        float2 f0 = __half22float2(*(__half2*)&pk.x);
        float2 f1 = __half22float2(*(__half2*)&pk.y);
        float2 f2 = __half22float2(*(__half2*)&pk.z);
        float2 f3 = __half22float2(*(__half2*)&pk.w);
        acc[0] = fmaf(f0.x, ee, acc[0]);
        acc[1] = fmaf(f0.y, ee, acc[1]);
        acc[2] = fmaf(f1.x, ee, acc[2]);
        acc[3] = fmaf(f1.y, ee, acc[3]);
        acc[4] = fmaf(f2.x, ee, acc[4]);
        acc[5] = fmaf(f2.y, ee, acc[5]);
        acc[6] = fmaf(f3.x, ee, acc[6]);
        acc[7] = fmaf(f3.y, ee, acc[7]);
        den += ee;
    }

    #pragma unroll
    for (int k = 0; k < 8; k++) {
        acc[k] += __shfl_xor_sync(0xffffffffu, acc[k], 8);
        acc[k] += __shfl_xor_sync(0xffffffffu, acc[k], 16);
    }
    den += __shfl_xor_sync(0xffffffffu, den, 8);
    den += __shfl_xor_sync(0xffffffffu, den, 16);

    float inv = (den > 0.0f) ? __fdividef(0.25f, den) : 0.0f;
    #pragma unroll
    for (int k = 0; k < 8; k++) acc[k] *= inv;

    #pragma unroll
    for (int k = 0; k < 8; k++) {
        acc[k] += __shfl_xor_sync(0xffffffffu, acc[k], 2);
        acc[k] += __shfl_xor_sync(0xffffffffu, acc[k], 4);
    }

    if (lane < 2) {
        float4 o0, o1;
        #pragma unroll
        for (int k = 0; k < 8; k++) {
            int dd = lane * 8 + k;
            float bm = 0.25f * (bias[dd] + bias[HID + dd]
                              + bias[2 * HID + dd] + bias[3 * HID + dd]);
            if (k < 4) ((float*)&o0)[k] = acc[k] + bm;
            else       ((float*)&o1)[k - 4] = acc[k] + bm;
        }
        *(float4*)&out[n * HID + lane * 8]     = o0;
        *(float4*)&out[n * HID + lane * 8 + 4] = o1;
    }
}

// ---------------- launch ------------------------------------------------------
extern "C" void kernel_launch(void* const* d_in, const int* in_sizes, int n_in,
                              void* d_out, int out_size) {
    const float* features = (const float*)d_in[0];
    const float* W        = (const float*)d_in[1];
    const float* attn_l   = (const float*)d_in[2];
    const float* attn_r   = (const float*)d_in[3];
    const float* bias     = (const float*)d_in[4];
    const void*  src_raw  = d_in[5];
    const void*  dst_raw  = d_in[6];
    float* out = (float*)d_out;

    const int T = 256;

    static cudaStream_t s_side = 0;
    static cudaEvent_t  ev_fork = 0, ev_join = 0;
    if (!s_side) {
        cudaStreamCreateWithFlags(&s_side, cudaStreamNonBlocking);
        cudaEventCreateWithFlags(&ev_fork, cudaEventDisableTiming);
        cudaEventCreateWithFlags(&ev_join, cudaEventDisableTiming);
    }

    // fork: GEMM on side stream; sort chain on main stream
    cudaEventRecord(ev_fork, 0);
    cudaStreamWaitEvent(s_side, ev_fork, 0);
    k_gemm<<<(N_NODES + BM - 1) / BM, T, 0, s_side>>>(features, W, attn_l, attn_r);
    cudaEventRecord(ev_join, s_side);

    k_hist<<<(N_EDGES / 4 + T - 1) / T, T>>>(dst_raw);
    k_scan<<<SCAN_BLOCKS, T>>>();
    k_fill<<<(N_EDGES / 4 + T - 1) / T, T>>>(src_raw, dst_raw);

    // join: aggregation needs both branches
    cudaStreamWaitEvent(0, ev_join, 0);
    k_agg<<<(N_NODES * 32 + T - 1) / T, T>>>(bias, out);
}